// round 4
// baseline (speedup 1.0000x reference)
#include <cuda_runtime.h>

#define Bv 2
#define Cv 64
#define Hv 128
#define Wv 128
#define HWv (Hv*Wv)

// Scratch buffers (static __device__ — no runtime allocation)
__device__ float g_s[Bv*Cv*HWv];      // o1+o2+o3 fused branch output
__device__ float g_off[Bv*18*HWv];    // 18 offset channels
__device__ float g_dsum[Bv*Cv*HWv];   // sum of 4 deformable convs

// ---------------------------------------------------------------------------
// Kernel 1: s = bn1(bias(dw 1x15)) + bn2(bias(dw 15x1)) + bn3(bias(dw 3x3))
// block = 32x8 pixels, one (b,c) per blockIdx.z, shared tile with halo 7
// ---------------------------------------------------------------------------
__global__ __launch_bounds__(256)
void k_branch(const float* __restrict__ x,
              const float* __restrict__ w1, const float* __restrict__ b1,
              const float* __restrict__ s1, const float* __restrict__ bb1,
              const float* __restrict__ w2, const float* __restrict__ b2,
              const float* __restrict__ s2, const float* __restrict__ bb2,
              const float* __restrict__ w3, const float* __restrict__ b3,
              const float* __restrict__ s3, const float* __restrict__ bb3)
{
    __shared__ float XS[22*46];
    __shared__ float WS[39];
    int tid = threadIdx.y*32 + threadIdx.x;
    int b = blockIdx.z / Cv, c = blockIdx.z % Cv;
    int gy0 = blockIdx.y*8, gx0 = blockIdx.x*32;
    const float* xc = x + (size_t)(b*Cv + c)*HWv;

    for (int i = tid; i < 22*46; i += 256) {
        int yy = i/46, xx = i%46;
        int gy = gy0 - 7 + yy, gx = gx0 - 7 + xx;
        XS[i] = (gy>=0 && gy<Hv && gx>=0 && gx<Wv) ? xc[gy*Wv+gx] : 0.f;
    }
    if (tid < 15)       WS[tid] = w1[c*15 + tid];
    else if (tid < 30)  WS[tid] = w2[c*15 + tid-15];
    else if (tid < 39)  WS[tid] = w3[c*9  + tid-30];
    __syncthreads();

    int tx = threadIdx.x, ty = threadIdx.y;
    float c1 = 0.f, c2 = 0.f, c3 = 0.f;
#pragma unroll
    for (int i = 0; i < 15; i++) c1 = fmaf(WS[i],    XS[(ty+7)*46 + tx + i], c1);
#pragma unroll
    for (int i = 0; i < 15; i++) c2 = fmaf(WS[15+i], XS[(ty+i)*46 + tx + 7], c2);
#pragma unroll
    for (int dy = 0; dy < 3; dy++)
#pragma unroll
        for (int dx = 0; dx < 3; dx++)
            c3 = fmaf(WS[30+dy*3+dx], XS[(ty+6+dy)*46 + tx+6+dx], c3);

    float a1 = s1[c], a2 = s2[c], a3 = s3[c];
    float cst = fmaf(a1, b1[c], bb1[c]) + fmaf(a2, b2[c], bb2[c]) + fmaf(a3, b3[c], bb3[c]);
    g_s[(size_t)(b*Cv+c)*HWv + (gy0+ty)*Wv + gx0+tx] =
        fmaf(a1, c1, fmaf(a2, c2, fmaf(a3, c3, cst)));
}

// ---------------------------------------------------------------------------
// Kernel 2: off = bn4(bias(1x1 conv C->18 of s))
// ---------------------------------------------------------------------------
__global__ __launch_bounds__(256)
void k_off(const float* __restrict__ balw, const float* __restrict__ balb,
           const float* __restrict__ s4,   const float* __restrict__ b4)
{
    __shared__ float BW[64*18];
    int tid = threadIdx.x;
    int b = blockIdx.y;
    int pix = blockIdx.x*256 + tid;
    for (int t = tid; t < 64*18; t += 256) {
        int c = t/18, j = t%18;
        BW[t] = balw[j*64 + c];           // BW[c*18+j]
    }
    __syncthreads();

    float acc[18];
#pragma unroll
    for (int j = 0; j < 18; j++) acc[j] = 0.f;

    const float* sp = g_s + (size_t)b*Cv*HWv + pix;
    for (int c = 0; c < 64; c++) {
        float v = sp[(size_t)c*HWv];
        const float* bwc = &BW[c*18];
#pragma unroll
        for (int j = 0; j < 18; j++) acc[j] = fmaf(bwc[j], v, acc[j]);
    }
#pragma unroll
    for (int j = 0; j < 18; j++)
        g_off[((size_t)b*18 + j)*HWv + pix] = fmaf(s4[j], acc[j] + balb[j], b4[j]);
}

// ---------------------------------------------------------------------------
// Kernel 3: sum of 4 deformable depthwise convs (d = 2,3,4,5), shared offsets.
// block = 32x8 pixels x 8 channels; x tile (46x22 per ch) staged in SMEM
// (halo 7, zero-padded outside image -> border masking is free).
// ---------------------------------------------------------------------------
__global__ __launch_bounds__(256)
void k_deform(const float* __restrict__ x,
              const float* __restrict__ dw2, const float* __restrict__ dw3,
              const float* __restrict__ dw4, const float* __restrict__ dw5)
{
    __shared__ float XS[8*1012];   // 8 channels x 22 rows x 46 cols
    __shared__ float DWT[288];     // [di][ci][k]
    int tid = threadIdx.y*32 + threadIdx.x;
    int b  = blockIdx.z >> 3;
    int c0 = (blockIdx.z & 7) * 8;
    int gy0 = blockIdx.y*8, gx0 = blockIdx.x*32;
    const float* xb = x + (size_t)(b*Cv + c0)*HWv;

    for (int i = tid; i < 8*1012; i += 256) {
        int c = i / 1012, r = i % 1012;
        int yy = r / 46, xx = r % 46;
        int gy = gy0 - 7 + yy, gx = gx0 - 7 + xx;
        XS[i] = (gy>=0 && gy<Hv && gx>=0 && gx<Wv) ? xb[(size_t)c*HWv + gy*Wv + gx] : 0.f;
    }
    // FIX (R3 bug): 288 > blockDim (256) — stride the load so DWT[256..287]
    // (tail of dw5) actually gets written.
    for (int t = tid; t < 288; t += 256) {
        int di = t/72, r = t%72, ci = r/9, k = r%9;
        const float* dp = (di==0)?dw2:(di==1)?dw3:(di==2)?dw4:dw5;
        DWT[t] = dp[(c0+ci)*9 + k];
    }
    __syncthreads();

    int gw = gx0 + threadIdx.x, gh = gy0 + threadIdx.y;
    int pix = gh*Wv + gw;

    float offy[9], offx[9];
    const float* op = g_off + (size_t)b*18*HWv + pix;
#pragma unroll
    for (int k = 0; k < 9; k++) {
        offy[k] = op[(size_t)(2*k  )*HWv];
        offx[k] = op[(size_t)(2*k+1)*HWv];
    }

    float acc[8];
#pragma unroll
    for (int ci = 0; ci < 8; ci++) acc[ci] = 0.f;

    for (int di = 0; di < 4; di++) {
        int d = di + 2;
#pragma unroll
        for (int k = 0; k < 9; k++) {
            int ky = k/3 - 1, kx = k%3 - 1;
            float py = offy[k] + (float)(gh + d*ky);
            float px = offx[k] + (float)(gw + d*kx);
            float y0f = floorf(py), x0f = floorf(px);
            float wy = py - y0f,   wx = px - x0f;
            int y0 = (int)y0f, x0 = (int)x0f;
            int sy = y0 - gy0 + 7, sx = x0 - gx0 + 7;
            float w11 = wy*wx;
            float w10 = wy - w11;
            float w01 = wx - w11;
            float w00 = 1.f - wy - wx + w11;
            const float* dwk = &DWT[di*72 + k];
            if (sy >= 0 && sy <= 20 && sx >= 0 && sx <= 44) {
                int base = sy*46 + sx;
#pragma unroll
                for (int ci = 0; ci < 8; ci++) {
                    const float* xc = &XS[ci*1012 + base];
                    float v = w00*xc[0] + w01*xc[1] + w10*xc[46] + w11*xc[47];
                    acc[ci] = fmaf(dwk[ci*9], v, acc[ci]);
                }
            } else {
                int y1 = y0 + 1, x1 = x0 + 1;
                bool vy0 = (y0>=0)&&(y0<Hv), vy1 = (y1>=0)&&(y1<Hv);
                bool vx0 = (x0>=0)&&(x0<Wv), vx1 = (x1>=0)&&(x1<Wv);
                int iy0 = vy0? y0:0, iy1 = vy1? y1:0;
                int ix0 = vx0? x0:0, ix1 = vx1? x1:0;
#pragma unroll
                for (int ci = 0; ci < 8; ci++) {
                    const float* xc = xb + (size_t)ci*HWv;
                    float g00 = (vy0&&vx0)? xc[iy0*Wv+ix0] : 0.f;
                    float g01 = (vy0&&vx1)? xc[iy0*Wv+ix1] : 0.f;
                    float g10 = (vy1&&vx0)? xc[iy1*Wv+ix0] : 0.f;
                    float g11 = (vy1&&vx1)? xc[iy1*Wv+ix1] : 0.f;
                    float v = w00*g00 + w01*g01 + w10*g10 + w11*g11;
                    acc[ci] = fmaf(dwk[ci*9], v, acc[ci]);
                }
            }
        }
    }
    float* outp = g_dsum + (size_t)(b*Cv + c0)*HWv + pix;
#pragma unroll
    for (int ci = 0; ci < 8; ci++) outp[(size_t)ci*HWv] = acc[ci];
}

// ---------------------------------------------------------------------------
// Kernel 4: out = bn5(bias(1x1 conv 64x64 of dsum)) * x
// ---------------------------------------------------------------------------
__global__ __launch_bounds__(256)
void k_final(const float* __restrict__ x,
             const float* __restrict__ fw, const float* __restrict__ fb,
             const float* __restrict__ s5, const float* __restrict__ b5,
             float* __restrict__ out)
{
    __shared__ float FW[4096];     // FW[cin*64+cout] = fin_w[cout*64+cin]
    int tid = threadIdx.x;
    int b = blockIdx.y;
    int pix = blockIdx.x*256 + tid;
    for (int t = tid; t < 4096; t += 256)
        FW[t] = fw[(t%64)*64 + t/64];
    __syncthreads();

    float acc[64];
#pragma unroll
    for (int j = 0; j < 64; j++) acc[j] = 0.f;

    const float* dp = g_dsum + (size_t)b*Cv*HWv + pix;
    for (int cin = 0; cin < 64; cin++) {
        float v = dp[(size_t)cin*HWv];
        const float* fwr = &FW[cin*64];
#pragma unroll
        for (int j = 0; j < 64; j++) acc[j] = fmaf(fwr[j], v, acc[j]);
    }

    const float* xp = x   + (size_t)b*Cv*HWv + pix;
    float*       opo = out + (size_t)b*Cv*HWv + pix;
    for (int j = 0; j < 64; j++) {
        float r = fmaf(s5[j], acc[j] + fb[j], b5[j]);
        opo[(size_t)j*HWv] = r * xp[(size_t)j*HWv];
    }
}

// ---------------------------------------------------------------------------
extern "C" void kernel_launch(void* const* d_in, const int* in_sizes, int n_in,
                              void* d_out, int out_size)
{
    // Input-order handling: metadata order is normally the reference-signature
    // (dict insertion) order, with x (2097152 elems) first. If the harness
    // instead sorted keys alphabetically, in_sizes[0] would be bal_b (18).
    // Disambiguate by size — cheap and deterministic.
    int ix, i_off1w, i_off1b, i_bn1s, i_bn1b, i_off2w, i_off2b, i_bn2s, i_bn2b,
        i_off3w, i_off3b, i_bn3s, i_bn3b, i_balw, i_balb, i_bn4s, i_bn4b,
        i_dw2, i_dw3, i_dw4, i_dw5, i_finw, i_finb, i_bn5s, i_bn5b;

    if (in_sizes[0] == Bv*Cv*HWv) {
        // signature / insertion order
        ix=0;  i_off1w=1;  i_off1b=2;  i_bn1s=3;  i_bn1b=4;
        i_off2w=5;  i_off2b=6;  i_bn2s=7;  i_bn2b=8;
        i_off3w=9;  i_off3b=10; i_bn3s=11; i_bn3b=12;
        i_balw=13; i_balb=14; i_bn4s=15; i_bn4b=16;
        i_dw2=17; i_dw3=18; i_dw4=19; i_dw5=20;
        i_finw=21; i_finb=22; i_bn5s=23; i_bn5b=24;
    } else {
        // alphabetical order: bal_b, bal_w, bn1_b, bn1_s, bn2_b, bn2_s,
        // bn3_b, bn3_s, bn4_b, bn4_s, bn5_b, bn5_s, dw2, dw3, dw4, dw5,
        // fin_b, fin_w, off1_b, off1_w, off2_b, off2_w, off3_b, off3_w, x
        i_balb=0; i_balw=1; i_bn1b=2; i_bn1s=3; i_bn2b=4; i_bn2s=5;
        i_bn3b=6; i_bn3s=7; i_bn4b=8; i_bn4s=9; i_bn5b=10; i_bn5s=11;
        i_dw2=12; i_dw3=13; i_dw4=14; i_dw5=15;
        i_finb=16; i_finw=17; i_off1b=18; i_off1w=19;
        i_off2b=20; i_off2w=21; i_off3b=22; i_off3w=23; ix=24;
    }

    const float* x      = (const float*)d_in[ix];
    const float* off1_w = (const float*)d_in[i_off1w];
    const float* off1_b = (const float*)d_in[i_off1b];
    const float* bn1_s  = (const float*)d_in[i_bn1s];
    const float* bn1_b  = (const float*)d_in[i_bn1b];
    const float* off2_w = (const float*)d_in[i_off2w];
    const float* off2_b = (const float*)d_in[i_off2b];
    const float* bn2_s  = (const float*)d_in[i_bn2s];
    const float* bn2_b  = (const float*)d_in[i_bn2b];
    const float* off3_w = (const float*)d_in[i_off3w];
    const float* off3_b = (const float*)d_in[i_off3b];
    const float* bn3_s  = (const float*)d_in[i_bn3s];
    const float* bn3_b  = (const float*)d_in[i_bn3b];
    const float* bal_w  = (const float*)d_in[i_balw];
    const float* bal_b  = (const float*)d_in[i_balb];
    const float* bn4_s  = (const float*)d_in[i_bn4s];
    const float* bn4_b  = (const float*)d_in[i_bn4b];
    const float* dw2    = (const float*)d_in[i_dw2];
    const float* dw3    = (const float*)d_in[i_dw3];
    const float* dw4    = (const float*)d_in[i_dw4];
    const float* dw5    = (const float*)d_in[i_dw5];
    const float* fin_w  = (const float*)d_in[i_finw];
    const float* fin_b  = (const float*)d_in[i_finb];
    const float* bn5_s  = (const float*)d_in[i_bn5s];
    const float* bn5_b  = (const float*)d_in[i_bn5b];
    float* out = (float*)d_out;

    dim3 blk(32, 8);
    k_branch<<<dim3(4, 16, Bv*Cv), blk>>>(x,
        off1_w, off1_b, bn1_s, bn1_b,
        off2_w, off2_b, bn2_s, bn2_b,
        off3_w, off3_b, bn3_s, bn3_b);
    k_off<<<dim3(HWv/256, Bv), 256>>>(bal_w, bal_b, bn4_s, bn4_b);
    k_deform<<<dim3(4, 16, Bv*8), blk>>>(x, dw2, dw3, dw4, dw5);
    k_final<<<dim3(HWv/256, Bv), 256>>>(x, fin_w, fin_b, bn5_s, bn5_b, out);
}

// round 6
// speedup vs baseline: 1.0860x; 1.0860x over previous
#include <cuda_runtime.h>

#define Bv 2
#define Cv 64
#define Hv 128
#define Wv 128
#define HWv (Hv*Wv)

// Scratch buffers (static __device__ — no runtime allocation)
__device__ float g_s[Bv*Cv*HWv];      // o1+o2+o3 fused branch output
__device__ float g_off[Bv*18*HWv];    // 18 offset channels
__device__ float g_dsum[Bv*Cv*HWv];   // sum of 4 deformable convs

// ---------------------------------------------------------------------------
// Kernel 1: s = bn1(bias(dw 1x15)) + bn2(bias(dw 15x1)) + bn3(bias(dw 3x3))
// ---------------------------------------------------------------------------
__global__ __launch_bounds__(256)
void k_branch(const float* __restrict__ x,
              const float* __restrict__ w1, const float* __restrict__ b1,
              const float* __restrict__ s1, const float* __restrict__ bb1,
              const float* __restrict__ w2, const float* __restrict__ b2,
              const float* __restrict__ s2, const float* __restrict__ bb2,
              const float* __restrict__ w3, const float* __restrict__ b3,
              const float* __restrict__ s3, const float* __restrict__ bb3)
{
    __shared__ float XS[22*46];
    __shared__ float WS[39];
    int tid = threadIdx.y*32 + threadIdx.x;
    int b = blockIdx.z / Cv, c = blockIdx.z % Cv;
    int gy0 = blockIdx.y*8, gx0 = blockIdx.x*32;
    const float* xc = x + (size_t)(b*Cv + c)*HWv;

    for (int i = tid; i < 22*46; i += 256) {
        int yy = i/46, xx = i%46;
        int gy = gy0 - 7 + yy, gx = gx0 - 7 + xx;
        XS[i] = (gy>=0 && gy<Hv && gx>=0 && gx<Wv) ? xc[gy*Wv+gx] : 0.f;
    }
    if (tid < 15)       WS[tid] = w1[c*15 + tid];
    else if (tid < 30)  WS[tid] = w2[c*15 + tid-15];
    else if (tid < 39)  WS[tid] = w3[c*9  + tid-30];
    __syncthreads();

    int tx = threadIdx.x, ty = threadIdx.y;
    float c1 = 0.f, c2 = 0.f, c3 = 0.f;
#pragma unroll
    for (int i = 0; i < 15; i++) c1 = fmaf(WS[i],    XS[(ty+7)*46 + tx + i], c1);
#pragma unroll
    for (int i = 0; i < 15; i++) c2 = fmaf(WS[15+i], XS[(ty+i)*46 + tx + 7], c2);
#pragma unroll
    for (int dy = 0; dy < 3; dy++)
#pragma unroll
        for (int dx = 0; dx < 3; dx++)
            c3 = fmaf(WS[30+dy*3+dx], XS[(ty+6+dy)*46 + tx+6+dx], c3);

    float a1 = s1[c], a2 = s2[c], a3 = s3[c];
    float cst = fmaf(a1, b1[c], bb1[c]) + fmaf(a2, b2[c], bb2[c]) + fmaf(a3, b3[c], bb3[c]);
    g_s[(size_t)(b*Cv+c)*HWv + (gy0+ty)*Wv + gx0+tx] =
        fmaf(a1, c1, fmaf(a2, c2, fmaf(a3, c3, cst)));
}

// ---------------------------------------------------------------------------
// Kernel 2: off = bn4(bias(1x1 conv C->18 of s))
// 64-thread blocks -> 512 blocks so the strided-load latency is hidden by
// block-level parallelism (R4: 128 blocks left the chip 12.5% occupied).
// ---------------------------------------------------------------------------
__global__ __launch_bounds__(64)
void k_off(const float* __restrict__ balw, const float* __restrict__ balb,
           const float* __restrict__ s4,   const float* __restrict__ b4)
{
    __shared__ float BW[64*18];
    int tid = threadIdx.x;
    int b = blockIdx.y;
    int pix = blockIdx.x*64 + tid;
    for (int t = tid; t < 64*18; t += 64) {
        int c = t/18, j = t%18;
        BW[t] = balw[j*64 + c];           // BW[c*18+j]
    }
    __syncthreads();

    float acc[18];
#pragma unroll
    for (int j = 0; j < 18; j++) acc[j] = 0.f;

    const float* sp = g_s + (size_t)b*Cv*HWv + pix;
#pragma unroll 4
    for (int c = 0; c < 64; c++) {
        float v = sp[(size_t)c*HWv];
        const float* bwc = &BW[c*18];
#pragma unroll
        for (int j = 0; j < 18; j++) acc[j] = fmaf(bwc[j], v, acc[j]);
    }
#pragma unroll
    for (int j = 0; j < 18; j++)
        g_off[((size_t)b*18 + j)*HWv + pix] = fmaf(s4[j], acc[j] + balb[j], b4[j]);
}

// ---------------------------------------------------------------------------
// Kernel 3: sum of 4 deformable depthwise convs (d = 2,3,4,5), shared offsets.
// ---------------------------------------------------------------------------
__global__ __launch_bounds__(256)
void k_deform(const float* __restrict__ x,
              const float* __restrict__ dw2, const float* __restrict__ dw3,
              const float* __restrict__ dw4, const float* __restrict__ dw5)
{
    __shared__ float XS[8*1012];   // 8 channels x 22 rows x 46 cols
    __shared__ float DWT[288];     // [di][ci][k]
    int tid = threadIdx.y*32 + threadIdx.x;
    int b  = blockIdx.z >> 3;
    int c0 = (blockIdx.z & 7) * 8;
    int gy0 = blockIdx.y*8, gx0 = blockIdx.x*32;
    const float* xb = x + (size_t)(b*Cv + c0)*HWv;

    for (int i = tid; i < 8*1012; i += 256) {
        int c = i / 1012, r = i % 1012;
        int yy = r / 46, xx = r % 46;
        int gy = gy0 - 7 + yy, gx = gx0 - 7 + xx;
        XS[i] = (gy>=0 && gy<Hv && gx>=0 && gx<Wv) ? xb[(size_t)c*HWv + gy*Wv + gx] : 0.f;
    }
    for (int t = tid; t < 288; t += 256) {
        int di = t/72, r = t%72, ci = r/9, k = r%9;
        const float* dp = (di==0)?dw2:(di==1)?dw3:(di==2)?dw4:dw5;
        DWT[t] = dp[(c0+ci)*9 + k];
    }
    __syncthreads();

    int gw = gx0 + threadIdx.x, gh = gy0 + threadIdx.y;
    int pix = gh*Wv + gw;

    float offy[9], offx[9];
    const float* op = g_off + (size_t)b*18*HWv + pix;
#pragma unroll
    for (int k = 0; k < 9; k++) {
        offy[k] = op[(size_t)(2*k  )*HWv];
        offx[k] = op[(size_t)(2*k+1)*HWv];
    }

    float acc[8];
#pragma unroll
    for (int ci = 0; ci < 8; ci++) acc[ci] = 0.f;

    for (int di = 0; di < 4; di++) {
        int d = di + 2;
#pragma unroll
        for (int k = 0; k < 9; k++) {
            int ky = k/3 - 1, kx = k%3 - 1;
            float py = offy[k] + (float)(gh + d*ky);
            float px = offx[k] + (float)(gw + d*kx);
            float y0f = floorf(py), x0f = floorf(px);
            float wy = py - y0f,   wx = px - x0f;
            int y0 = (int)y0f, x0 = (int)x0f;
            int sy = y0 - gy0 + 7, sx = x0 - gx0 + 7;
            float w11 = wy*wx;
            float w10 = wy - w11;
            float w01 = wx - w11;
            float w00 = 1.f - wy - wx + w11;
            const float* dwk = &DWT[di*72 + k];
            if (sy >= 0 && sy <= 20 && sx >= 0 && sx <= 44) {
                int base = sy*46 + sx;
#pragma unroll
                for (int ci = 0; ci < 8; ci++) {
                    const float* xc = &XS[ci*1012 + base];
                    float v = w00*xc[0] + w01*xc[1] + w10*xc[46] + w11*xc[47];
                    acc[ci] = fmaf(dwk[ci*9], v, acc[ci]);
                }
            } else {
                int y1 = y0 + 1, x1 = x0 + 1;
                bool vy0 = (y0>=0)&&(y0<Hv), vy1 = (y1>=0)&&(y1<Hv);
                bool vx0 = (x0>=0)&&(x0<Wv), vx1 = (x1>=0)&&(x1<Wv);
                int iy0 = vy0? y0:0, iy1 = vy1? y1:0;
                int ix0 = vx0? x0:0, ix1 = vx1? x1:0;
#pragma unroll
                for (int ci = 0; ci < 8; ci++) {
                    const float* xc = xb + (size_t)ci*HWv;
                    float g00 = (vy0&&vx0)? xc[iy0*Wv+ix0] : 0.f;
                    float g01 = (vy0&&vx1)? xc[iy0*Wv+ix1] : 0.f;
                    float g10 = (vy1&&vx0)? xc[iy1*Wv+ix0] : 0.f;
                    float g11 = (vy1&&vx1)? xc[iy1*Wv+ix1] : 0.f;
                    float v = w00*g00 + w01*g01 + w10*g10 + w11*g11;
                    acc[ci] = fmaf(dwk[ci*9], v, acc[ci]);
                }
            }
        }
    }
    float* outp = g_dsum + (size_t)(b*Cv + c0)*HWv + pix;
#pragma unroll
    for (int ci = 0; ci < 8; ci++) outp[(size_t)ci*HWv] = acc[ci];
}

// ---------------------------------------------------------------------------
// Kernel 4 (rewritten): out = bn5(bias(fin_w @ dsum)) * x as a tiled GEMM.
// Block tile: 64 couts x 64 pixels, full cin=64 in SMEM (16KB + 16KB).
// 16x16 threads, each computes a 4x4 (cout x pixel) register tile with
// float4 LDS. Grid = 512 blocks (was 128 -> latency-bound at 12.5% occ).
// ---------------------------------------------------------------------------
__global__ __launch_bounds__(256)
void k_final(const float* __restrict__ x,
             const float* __restrict__ fw, const float* __restrict__ fb,
             const float* __restrict__ s5, const float* __restrict__ b5,
             float* __restrict__ out)
{
    __shared__ float FWs[64*64];   // FWs[cin*64+cout] = fin_w[cout*64+cin]
    __shared__ float DS[64*64];    // DS[cin*64+p] = dsum[b][cin][pix0+p]
    int tid = threadIdx.x;
    int b = blockIdx.y;
    int pix0 = blockIdx.x*64;

    const float* dp = g_dsum + (size_t)b*Cv*HWv + pix0;
    for (int i = tid; i < 4096; i += 256) {
        FWs[i] = fw[(i & 63)*64 + (i >> 6)];
        int cin = i >> 6, p = i & 63;
        DS[i] = dp[(size_t)cin*HWv + p];
    }
    __syncthreads();

    int tp = tid & 15;        // pixel group: pixels tp*4 .. tp*4+3
    int tc = tid >> 4;        // cout group:  couts  tc*4 .. tc*4+3
    float4 a0 = {0,0,0,0}, a1 = {0,0,0,0}, a2 = {0,0,0,0}, a3 = {0,0,0,0};

#pragma unroll 8
    for (int cin = 0; cin < 64; cin++) {
        float4 d = *(const float4*)&DS [cin*64 + tp*4];
        float4 w = *(const float4*)&FWs[cin*64 + tc*4];
        a0.x = fmaf(w.x, d.x, a0.x); a0.y = fmaf(w.x, d.y, a0.y);
        a0.z = fmaf(w.x, d.z, a0.z); a0.w = fmaf(w.x, d.w, a0.w);
        a1.x = fmaf(w.y, d.x, a1.x); a1.y = fmaf(w.y, d.y, a1.y);
        a1.z = fmaf(w.y, d.z, a1.z); a1.w = fmaf(w.y, d.w, a1.w);
        a2.x = fmaf(w.z, d.x, a2.x); a2.y = fmaf(w.z, d.y, a2.y);
        a2.z = fmaf(w.z, d.z, a2.z); a2.w = fmaf(w.z, d.w, a2.w);
        a3.x = fmaf(w.w, d.x, a3.x); a3.y = fmaf(w.w, d.y, a3.y);
        a3.z = fmaf(w.w, d.z, a3.z); a3.w = fmaf(w.w, d.w, a3.w);
    }

    float4 accs[4] = {a0, a1, a2, a3};
#pragma unroll
    for (int i = 0; i < 4; i++) {
        int j = tc*4 + i;
        float sc = s5[j], fbj = fb[j], bbj = b5[j];
        size_t o = (size_t)(b*Cv + j)*HWv + pix0 + tp*4;
        float4 xv = *(const float4*)(x + o);
        float4 r;
        r.x = fmaf(sc, accs[i].x + fbj, bbj) * xv.x;
        r.y = fmaf(sc, accs[i].y + fbj, bbj) * xv.y;
        r.z = fmaf(sc, accs[i].z + fbj, bbj) * xv.z;
        r.w = fmaf(sc, accs[i].w + fbj, bbj) * xv.w;
        *(float4*)(out + o) = r;
    }
}

// ---------------------------------------------------------------------------
extern "C" void kernel_launch(void* const* d_in, const int* in_sizes, int n_in,
                              void* d_out, int out_size)
{
    int ix, i_off1w, i_off1b, i_bn1s, i_bn1b, i_off2w, i_off2b, i_bn2s, i_bn2b,
        i_off3w, i_off3b, i_bn3s, i_bn3b, i_balw, i_balb, i_bn4s, i_bn4b,
        i_dw2, i_dw3, i_dw4, i_dw5, i_finw, i_finb, i_bn5s, i_bn5b;

    if (in_sizes[0] == Bv*Cv*HWv) {
        ix=0;  i_off1w=1;  i_off1b=2;  i_bn1s=3;  i_bn1b=4;
        i_off2w=5;  i_off2b=6;  i_bn2s=7;  i_bn2b=8;
        i_off3w=9;  i_off3b=10; i_bn3s=11; i_bn3b=12;
        i_balw=13; i_balb=14; i_bn4s=15; i_bn4b=16;
        i_dw2=17; i_dw3=18; i_dw4=19; i_dw5=20;
        i_finw=21; i_finb=22; i_bn5s=23; i_bn5b=24;
    } else {
        i_balb=0; i_balw=1; i_bn1b=2; i_bn1s=3; i_bn2b=4; i_bn2s=5;
        i_bn3b=6; i_bn3s=7; i_bn4b=8; i_bn4s=9; i_bn5b=10; i_bn5s=11;
        i_dw2=12; i_dw3=13; i_dw4=14; i_dw5=15;
        i_finb=16; i_finw=17; i_off1b=18; i_off1w=19;
        i_off2b=20; i_off2w=21; i_off3b=22; i_off3w=23; ix=24;
    }

    const float* x      = (const float*)d_in[ix];
    const float* off1_w = (const float*)d_in[i_off1w];
    const float* off1_b = (const float*)d_in[i_off1b];
    const float* bn1_s  = (const float*)d_in[i_bn1s];
    const float* bn1_b  = (const float*)d_in[i_bn1b];
    const float* off2_w = (const float*)d_in[i_off2w];
    const float* off2_b = (const float*)d_in[i_off2b];
    const float* bn2_s  = (const float*)d_in[i_bn2s];
    const float* bn2_b  = (const float*)d_in[i_bn2b];
    const float* off3_w = (const float*)d_in[i_off3w];
    const float* off3_b = (const float*)d_in[i_off3b];
    const float* bn3_s  = (const float*)d_in[i_bn3s];
    const float* bn3_b  = (const float*)d_in[i_bn3b];
    const float* bal_w  = (const float*)d_in[i_balw];
    const float* bal_b  = (const float*)d_in[i_balb];
    const float* bn4_s  = (const float*)d_in[i_bn4s];
    const float* bn4_b  = (const float*)d_in[i_bn4b];
    const float* dw2    = (const float*)d_in[i_dw2];
    const float* dw3    = (const float*)d_in[i_dw3];
    const float* dw4    = (const float*)d_in[i_dw4];
    const float* dw5    = (const float*)d_in[i_dw5];
    const float* fin_w  = (const float*)d_in[i_finw];
    const float* fin_b  = (const float*)d_in[i_finb];
    const float* bn5_s  = (const float*)d_in[i_bn5s];
    const float* bn5_b  = (const float*)d_in[i_bn5b];
    float* out = (float*)d_out;

    dim3 blk(32, 8);
    k_branch<<<dim3(4, 16, Bv*Cv), blk>>>(x,
        off1_w, off1_b, bn1_s, bn1_b,
        off2_w, off2_b, bn2_s, bn2_b,
        off3_w, off3_b, bn3_s, bn3_b);
    k_off<<<dim3(HWv/64, Bv), 64>>>(bal_w, bal_b, bn4_s, bn4_b);
    k_deform<<<dim3(4, 16, Bv*8), blk>>>(x, dw2, dw3, dw4, dw5);
    k_final<<<dim3(HWv/64, Bv), 256>>>(x, fin_w, fin_b, bn5_s, bn5_b, out);
}

// round 7
// speedup vs baseline: 1.1955x; 1.1008x over previous
#include <cuda_runtime.h>

#define Bv 2
#define Cv 64
#define Hv 128
#define Wv 128
#define HWv (Hv*Wv)

// Scratch buffers (static __device__ — no runtime allocation)
__device__ float g_s[Bv*Cv*HWv];      // o1+o2+o3 fused branch output
__device__ float g_off[Bv*18*HWv];    // 18 offset channels
__device__ float g_dsum[Bv*Cv*HWv];   // sum of 4 deformable convs

// ---------------------------------------------------------------------------
// Kernel 1: s = bn1(bias(dw 1x15)) + bn2(bias(dw 15x1)) + bn3(bias(dw 3x3))
// ---------------------------------------------------------------------------
__global__ __launch_bounds__(256)
void k_branch(const float* __restrict__ x,
              const float* __restrict__ w1, const float* __restrict__ b1,
              const float* __restrict__ s1, const float* __restrict__ bb1,
              const float* __restrict__ w2, const float* __restrict__ b2,
              const float* __restrict__ s2, const float* __restrict__ bb2,
              const float* __restrict__ w3, const float* __restrict__ b3,
              const float* __restrict__ s3, const float* __restrict__ bb3)
{
    __shared__ float XS[22*46];
    __shared__ float WS[39];
    int tid = threadIdx.y*32 + threadIdx.x;
    int b = blockIdx.z / Cv, c = blockIdx.z % Cv;
    int gy0 = blockIdx.y*8, gx0 = blockIdx.x*32;
    const float* xc = x + (size_t)(b*Cv + c)*HWv;

    for (int i = tid; i < 22*46; i += 256) {
        int yy = i/46, xx = i%46;
        int gy = gy0 - 7 + yy, gx = gx0 - 7 + xx;
        XS[i] = (gy>=0 && gy<Hv && gx>=0 && gx<Wv) ? xc[gy*Wv+gx] : 0.f;
    }
    if (tid < 15)       WS[tid] = w1[c*15 + tid];
    else if (tid < 30)  WS[tid] = w2[c*15 + tid-15];
    else if (tid < 39)  WS[tid] = w3[c*9  + tid-30];
    __syncthreads();

    int tx = threadIdx.x, ty = threadIdx.y;
    float c1 = 0.f, c2 = 0.f, c3 = 0.f;
#pragma unroll
    for (int i = 0; i < 15; i++) c1 = fmaf(WS[i],    XS[(ty+7)*46 + tx + i], c1);
#pragma unroll
    for (int i = 0; i < 15; i++) c2 = fmaf(WS[15+i], XS[(ty+i)*46 + tx + 7], c2);
#pragma unroll
    for (int dy = 0; dy < 3; dy++)
#pragma unroll
        for (int dx = 0; dx < 3; dx++)
            c3 = fmaf(WS[30+dy*3+dx], XS[(ty+6+dy)*46 + tx+6+dx], c3);

    float a1 = s1[c], a2 = s2[c], a3 = s3[c];
    float cst = fmaf(a1, b1[c], bb1[c]) + fmaf(a2, b2[c], bb2[c]) + fmaf(a3, b3[c], bb3[c]);
    g_s[(size_t)(b*Cv+c)*HWv + (gy0+ty)*Wv + gx0+tx] =
        fmaf(a1, c1, fmaf(a2, c2, fmaf(a3, c3, cst)));
}

// ---------------------------------------------------------------------------
// Kernel 2: off = bn4(bias(1x1 conv C->18 of s))
// ---------------------------------------------------------------------------
__global__ __launch_bounds__(64)
void k_off(const float* __restrict__ balw, const float* __restrict__ balb,
           const float* __restrict__ s4,   const float* __restrict__ b4)
{
    __shared__ float BW[64*18];
    int tid = threadIdx.x;
    int b = blockIdx.y;
    int pix = blockIdx.x*64 + tid;
    for (int t = tid; t < 64*18; t += 64) {
        int c = t/18, j = t%18;
        BW[t] = balw[j*64 + c];           // BW[c*18+j]
    }
    __syncthreads();

    float acc[18];
#pragma unroll
    for (int j = 0; j < 18; j++) acc[j] = 0.f;

    const float* sp = g_s + (size_t)b*Cv*HWv + pix;
#pragma unroll 4
    for (int c = 0; c < 64; c++) {
        float v = sp[(size_t)c*HWv];
        const float* bwc = &BW[c*18];
#pragma unroll
        for (int j = 0; j < 18; j++) acc[j] = fmaf(bwc[j], v, acc[j]);
    }
#pragma unroll
    for (int j = 0; j < 18; j++)
        g_off[((size_t)b*18 + j)*HWv + pix] = fmaf(s4[j], acc[j] + balb[j], b4[j]);
}

// ---------------------------------------------------------------------------
// Kernel 3: sum of 4 deformable depthwise convs (d = 2,3,4,5), shared offsets.
// Channel-interleaved SMEM: XS[loc*8 + (ci ^ (loc&4))] — each bilinear corner
// for 8 channels = 2 conflict-free LDS.128. Bilinear fracs/weights computed
// once per k (shared across all 4 dilations: d*ky is integer).
// ---------------------------------------------------------------------------
#define CORNER(L, qa, qb) { int _s = ((L)>>2)&1; const float4* _p = (const float4*)XS + 2*(L); qa = _p[_s]; qb = _p[_s^1]; }

__global__ __launch_bounds__(256)
void k_deform(const float* __restrict__ x,
              const float* __restrict__ dw2, const float* __restrict__ dw3,
              const float* __restrict__ dw4, const float* __restrict__ dw5)
{
    __shared__ float XS[1012*8];   // [loc = yy*46+xx][ci swizzled]
    __shared__ float DWT[4*9*8];   // [di][k][ci]
    int tid = threadIdx.y*32 + threadIdx.x;
    int b  = blockIdx.z >> 3;
    int c0 = (blockIdx.z & 7) * 8;
    int gy0 = blockIdx.y*8, gx0 = blockIdx.x*32;
    const float* xb = x + (size_t)(b*Cv + c0)*HWv;

    for (int i = tid; i < 8096; i += 256) {
        int ci = i / 1012, loc = i % 1012;
        int yy = loc / 46, xx = loc % 46;
        int gy = gy0 - 7 + yy, gx = gx0 - 7 + xx;
        float v = (gy>=0 && gy<Hv && gx>=0 && gx<Wv) ? xb[(size_t)ci*HWv + gy*Wv + gx] : 0.f;
        XS[loc*8 + (ci ^ (loc & 4))] = v;
    }
    for (int t = tid; t < 288; t += 256) {
        int di = t/72, r = t%72, k = r/8, ci = r%8;
        const float* dp = (di==0)?dw2:(di==1)?dw3:(di==2)?dw4:dw5;
        DWT[t] = dp[(c0+ci)*9 + k];
    }
    __syncthreads();

    int gw = gx0 + threadIdx.x, gh = gy0 + threadIdx.y;
    int pix = gh*Wv + gw;

    float acc[8];
#pragma unroll
    for (int ci = 0; ci < 8; ci++) acc[ci] = 0.f;

    const float* op = g_off + (size_t)b*18*HWv + pix;

#pragma unroll
    for (int k = 0; k < 9; k++) {
        int ky = k/3 - 1, kx = k%3 - 1;
        float py = op[(size_t)(2*k  )*HWv] + (float)gh;
        float px = op[(size_t)(2*k+1)*HWv] + (float)gw;
        float fy = floorf(py), fx = floorf(px);
        float wy = py - fy, wx = px - fx;
        int y0b = (int)fy, x0b = (int)fx;
        float w11 = wy*wx;
        float w10 = wy - w11;
        float w01 = wx - w11;
        float w00 = 1.f - wy - wx + w11;

#pragma unroll
        for (int di = 0; di < 4; di++) {
            int d = di + 2;
            int y0 = y0b + d*ky, x0 = x0b + d*kx;
            int sy = y0 - gy0 + 7, sx = x0 - gx0 + 7;
            const float4* dwq = (const float4*)&DWT[(di*9 + k)*8];
            if (sy >= 0 && sy <= 20 && sx >= 0 && sx <= 44) {
                int L = sy*46 + sx;
                float4 p00a,p00b,p01a,p01b,p10a,p10b,p11a,p11b;
                CORNER(L,    p00a, p00b);
                CORNER(L+1,  p01a, p01b);
                CORNER(L+46, p10a, p10b);
                CORNER(L+47, p11a, p11b);
                float4 dq0 = dwq[0], dq1 = dwq[1];
                float v;
                v = w00*p00a.x + w01*p01a.x + w10*p10a.x + w11*p11a.x; acc[0] = fmaf(dq0.x, v, acc[0]);
                v = w00*p00a.y + w01*p01a.y + w10*p10a.y + w11*p11a.y; acc[1] = fmaf(dq0.y, v, acc[1]);
                v = w00*p00a.z + w01*p01a.z + w10*p10a.z + w11*p11a.z; acc[2] = fmaf(dq0.z, v, acc[2]);
                v = w00*p00a.w + w01*p01a.w + w10*p10a.w + w11*p11a.w; acc[3] = fmaf(dq0.w, v, acc[3]);
                v = w00*p00b.x + w01*p01b.x + w10*p10b.x + w11*p11b.x; acc[4] = fmaf(dq1.x, v, acc[4]);
                v = w00*p00b.y + w01*p01b.y + w10*p10b.y + w11*p11b.y; acc[5] = fmaf(dq1.y, v, acc[5]);
                v = w00*p00b.z + w01*p01b.z + w10*p10b.z + w11*p11b.z; acc[6] = fmaf(dq1.z, v, acc[6]);
                v = w00*p00b.w + w01*p01b.w + w10*p10b.w + w11*p11b.w; acc[7] = fmaf(dq1.w, v, acc[7]);
            } else {
                int y1 = y0 + 1, x1 = x0 + 1;
                bool vy0 = (y0>=0)&&(y0<Hv), vy1 = (y1>=0)&&(y1<Hv);
                bool vx0 = (x0>=0)&&(x0<Wv), vx1 = (x1>=0)&&(x1<Wv);
                int iy0 = vy0? y0:0, iy1 = vy1? y1:0;
                int ix0 = vx0? x0:0, ix1 = vx1? x1:0;
                const float* dwf = (const float*)dwq;
#pragma unroll
                for (int ci = 0; ci < 8; ci++) {
                    const float* xc = xb + (size_t)ci*HWv;
                    float g00 = (vy0&&vx0)? xc[iy0*Wv+ix0] : 0.f;
                    float g01 = (vy0&&vx1)? xc[iy0*Wv+ix1] : 0.f;
                    float g10 = (vy1&&vx0)? xc[iy1*Wv+ix0] : 0.f;
                    float g11 = (vy1&&vx1)? xc[iy1*Wv+ix1] : 0.f;
                    float v = w00*g00 + w01*g01 + w10*g10 + w11*g11;
                    acc[ci] = fmaf(dwf[ci], v, acc[ci]);
                }
            }
        }
    }
    float* outp = g_dsum + (size_t)(b*Cv + c0)*HWv + pix;
#pragma unroll
    for (int ci = 0; ci < 8; ci++) outp[(size_t)ci*HWv] = acc[ci];
}

// ---------------------------------------------------------------------------
// Kernel 4: out = bn5(bias(fin_w @ dsum)) * x, tiled GEMM.
// 64 couts x 64 px tile, 128 threads, thread tile = 8 couts x 4 px:
// 3 LDS.128 per 32 FMA (half the smem traffic of R6's 4x4).
// ---------------------------------------------------------------------------
__global__ __launch_bounds__(128)
void k_final(const float* __restrict__ x,
             const float* __restrict__ fw, const float* __restrict__ fb,
             const float* __restrict__ s5, const float* __restrict__ b5,
             float* __restrict__ out)
{
    __shared__ float FWs[64*64];   // FWs[cin*64+cout] = fin_w[cout*64+cin]
    __shared__ float DS[64*64];    // DS[cin*64+p]
    int tid = threadIdx.x;
    int b = blockIdx.y;
    int pix0 = blockIdx.x*64;

    const float* dp = g_dsum + (size_t)b*Cv*HWv + pix0;
    for (int i = tid; i < 4096; i += 128)
        FWs[i] = fw[(i & 63)*64 + (i >> 6)];
    for (int i = tid; i < 1024; i += 128) {
        int cin = i >> 4, p4 = i & 15;
        ((float4*)DS)[cin*16 + p4] = *(const float4*)(dp + (size_t)cin*HWv + p4*4);
    }
    __syncthreads();

    int tp = tid & 15;        // pixels tp*4 .. tp*4+3
    int tc = tid >> 4;        // couts  tc*8 .. tc*8+7
    float4 acc[8];
#pragma unroll
    for (int i = 0; i < 8; i++) acc[i] = make_float4(0.f,0.f,0.f,0.f);

#pragma unroll 4
    for (int cin = 0; cin < 64; cin++) {
        float4 d  = *(const float4*)&DS [cin*64 + tp*4];
        float4 w0 = *(const float4*)&FWs[cin*64 + tc*8];
        float4 w1 = *(const float4*)&FWs[cin*64 + tc*8 + 4];
        float wv[8] = {w0.x,w0.y,w0.z,w0.w,w1.x,w1.y,w1.z,w1.w};
#pragma unroll
        for (int i = 0; i < 8; i++) {
            acc[i].x = fmaf(wv[i], d.x, acc[i].x);
            acc[i].y = fmaf(wv[i], d.y, acc[i].y);
            acc[i].z = fmaf(wv[i], d.z, acc[i].z);
            acc[i].w = fmaf(wv[i], d.w, acc[i].w);
        }
    }

#pragma unroll
    for (int i = 0; i < 8; i++) {
        int j = tc*8 + i;
        float sc = s5[j], fbj = fb[j], bbj = b5[j];
        size_t o = (size_t)(b*Cv + j)*HWv + pix0 + tp*4;
        float4 xv = *(const float4*)(x + o);
        float4 r;
        r.x = fmaf(sc, acc[i].x + fbj, bbj) * xv.x;
        r.y = fmaf(sc, acc[i].y + fbj, bbj) * xv.y;
        r.z = fmaf(sc, acc[i].z + fbj, bbj) * xv.z;
        r.w = fmaf(sc, acc[i].w + fbj, bbj) * xv.w;
        *(float4*)(out + o) = r;
    }
}

// ---------------------------------------------------------------------------
extern "C" void kernel_launch(void* const* d_in, const int* in_sizes, int n_in,
                              void* d_out, int out_size)
{
    int ix, i_off1w, i_off1b, i_bn1s, i_bn1b, i_off2w, i_off2b, i_bn2s, i_bn2b,
        i_off3w, i_off3b, i_bn3s, i_bn3b, i_balw, i_balb, i_bn4s, i_bn4b,
        i_dw2, i_dw3, i_dw4, i_dw5, i_finw, i_finb, i_bn5s, i_bn5b;

    if (in_sizes[0] == Bv*Cv*HWv) {
        ix=0;  i_off1w=1;  i_off1b=2;  i_bn1s=3;  i_bn1b=4;
        i_off2w=5;  i_off2b=6;  i_bn2s=7;  i_bn2b=8;
        i_off3w=9;  i_off3b=10; i_bn3s=11; i_bn3b=12;
        i_balw=13; i_balb=14; i_bn4s=15; i_bn4b=16;
        i_dw2=17; i_dw3=18; i_dw4=19; i_dw5=20;
        i_finw=21; i_finb=22; i_bn5s=23; i_bn5b=24;
    } else {
        i_balb=0; i_balw=1; i_bn1b=2; i_bn1s=3; i_bn2b=4; i_bn2s=5;
        i_bn3b=6; i_bn3s=7; i_bn4b=8; i_bn4s=9; i_bn5b=10; i_bn5s=11;
        i_dw2=12; i_dw3=13; i_dw4=14; i_dw5=15;
        i_finb=16; i_finw=17; i_off1b=18; i_off1w=19;
        i_off2b=20; i_off2w=21; i_off3b=22; i_off3w=23; ix=24;
    }

    const float* x      = (const float*)d_in[ix];
    const float* off1_w = (const float*)d_in[i_off1w];
    const float* off1_b = (const float*)d_in[i_off1b];
    const float* bn1_s  = (const float*)d_in[i_bn1s];
    const float* bn1_b  = (const float*)d_in[i_bn1b];
    const float* off2_w = (const float*)d_in[i_off2w];
    const float* off2_b = (const float*)d_in[i_off2b];
    const float* bn2_s  = (const float*)d_in[i_bn2s];
    const float* bn2_b  = (const float*)d_in[i_bn2b];
    const float* off3_w = (const float*)d_in[i_off3w];
    const float* off3_b = (const float*)d_in[i_off3b];
    const float* bn3_s  = (const float*)d_in[i_bn3s];
    const float* bn3_b  = (const float*)d_in[i_bn3b];
    const float* bal_w  = (const float*)d_in[i_balw];
    const float* bal_b  = (const float*)d_in[i_balb];
    const float* bn4_s  = (const float*)d_in[i_bn4s];
    const float* bn4_b  = (const float*)d_in[i_bn4b];
    const float* dw2    = (const float*)d_in[i_dw2];
    const float* dw3    = (const float*)d_in[i_dw3];
    const float* dw4    = (const float*)d_in[i_dw4];
    const float* dw5    = (const float*)d_in[i_dw5];
    const float* fin_w  = (const float*)d_in[i_finw];
    const float* fin_b  = (const float*)d_in[i_finb];
    const float* bn5_s  = (const float*)d_in[i_bn5s];
    const float* bn5_b  = (const float*)d_in[i_bn5b];
    float* out = (float*)d_out;

    dim3 blk(32, 8);
    k_branch<<<dim3(4, 16, Bv*Cv), blk>>>(x,
        off1_w, off1_b, bn1_s, bn1_b,
        off2_w, off2_b, bn2_s, bn2_b,
        off3_w, off3_b, bn3_s, bn3_b);
    k_off<<<dim3(HWv/64, Bv), 64>>>(bal_w, bal_b, bn4_s, bn4_b);
    k_deform<<<dim3(4, 16, Bv*8), blk>>>(x, dw2, dw3, dw4, dw5);
    k_final<<<dim3(HWv/64, Bv), 128>>>(x, fin_w, fin_b, bn5_s, bn5_b, out);
}

// round 9
// speedup vs baseline: 1.4471x; 1.2104x over previous
#include <cuda_runtime.h>

#define Bv 2
#define Cv 64
#define Hv 128
#define Wv 128
#define HWv (Hv*Wv)

// Scratch buffers (static __device__ — no runtime allocation)
__device__ float g_s[Bv*Cv*HWv];      // o1+o2+o3 fused branch output
__device__ float g_off[Bv*18*HWv];    // 18 offset channels
__device__ float g_dsum[Bv*Cv*HWv];   // sum of 4 deformable convs

// ---------------------------------------------------------------------------
// Kernel 1: s = bn1(bias(dw 1x15)) + bn2(bias(dw 15x1)) + bn3(bias(dw 3x3))
// ---------------------------------------------------------------------------
__global__ __launch_bounds__(256)
void k_branch(const float* __restrict__ x,
              const float* __restrict__ w1, const float* __restrict__ b1,
              const float* __restrict__ s1, const float* __restrict__ bb1,
              const float* __restrict__ w2, const float* __restrict__ b2,
              const float* __restrict__ s2, const float* __restrict__ bb2,
              const float* __restrict__ w3, const float* __restrict__ b3,
              const float* __restrict__ s3, const float* __restrict__ bb3)
{
    __shared__ float XS[22*46];
    __shared__ float WS[39];
    int tid = threadIdx.y*32 + threadIdx.x;
    int b = blockIdx.z / Cv, c = blockIdx.z % Cv;
    int gy0 = blockIdx.y*8, gx0 = blockIdx.x*32;
    const float* xc = x + (size_t)(b*Cv + c)*HWv;

    for (int i = tid; i < 22*46; i += 256) {
        int yy = i/46, xx = i%46;
        int gy = gy0 - 7 + yy, gx = gx0 - 7 + xx;
        XS[i] = (gy>=0 && gy<Hv && gx>=0 && gx<Wv) ? xc[gy*Wv+gx] : 0.f;
    }
    if (tid < 15)       WS[tid] = w1[c*15 + tid];
    else if (tid < 30)  WS[tid] = w2[c*15 + tid-15];
    else if (tid < 39)  WS[tid] = w3[c*9  + tid-30];
    __syncthreads();

    int tx = threadIdx.x, ty = threadIdx.y;
    float c1 = 0.f, c2 = 0.f, c3 = 0.f;
#pragma unroll
    for (int i = 0; i < 15; i++) c1 = fmaf(WS[i],    XS[(ty+7)*46 + tx + i], c1);
#pragma unroll
    for (int i = 0; i < 15; i++) c2 = fmaf(WS[15+i], XS[(ty+i)*46 + tx + 7], c2);
#pragma unroll
    for (int dy = 0; dy < 3; dy++)
#pragma unroll
        for (int dx = 0; dx < 3; dx++)
            c3 = fmaf(WS[30+dy*3+dx], XS[(ty+6+dy)*46 + tx+6+dx], c3);

    float a1 = s1[c], a2 = s2[c], a3 = s3[c];
    float cst = fmaf(a1, b1[c], bb1[c]) + fmaf(a2, b2[c], bb2[c]) + fmaf(a3, b3[c], bb3[c]);
    g_s[(size_t)(b*Cv+c)*HWv + (gy0+ty)*Wv + gx0+tx] =
        fmaf(a1, c1, fmaf(a2, c2, fmaf(a3, c3, cst)));
}

// ---------------------------------------------------------------------------
// Kernel 2: off = bn4(bias(1x1 conv C->18 of s))
// ---------------------------------------------------------------------------
__global__ __launch_bounds__(64)
void k_off(const float* __restrict__ balw, const float* __restrict__ balb,
           const float* __restrict__ s4,   const float* __restrict__ b4)
{
    __shared__ float BW[64*18];
    int tid = threadIdx.x;
    int b = blockIdx.y;
    int pix = blockIdx.x*64 + tid;
    for (int t = tid; t < 64*18; t += 64) {
        int c = t/18, j = t%18;
        BW[t] = balw[j*64 + c];           // BW[c*18+j]
    }
    __syncthreads();

    float acc[18];
#pragma unroll
    for (int j = 0; j < 18; j++) acc[j] = 0.f;

    const float* sp = g_s + (size_t)b*Cv*HWv + pix;
#pragma unroll 8
    for (int c = 0; c < 64; c++) {
        float v = sp[(size_t)c*HWv];
        const float* bwc = &BW[c*18];
#pragma unroll
        for (int j = 0; j < 18; j++) acc[j] = fmaf(bwc[j], v, acc[j]);
    }
#pragma unroll
    for (int j = 0; j < 18; j++)
        g_off[((size_t)b*18 + j)*HWv + pix] = fmaf(s4[j], acc[j] + balb[j], b4[j]);
}

// ---------------------------------------------------------------------------
// Kernel 3: sum of 4 deformable depthwise convs (d = 2,3,4,5), shared offsets.
// Channel-interleaved SMEM: XS[loc*8 + (ci ^ (loc&4))] — each bilinear corner
// for 8 channels = 2 LDS.128. Bilinear fracs/weights computed once per k
// (shared across dilations). NEW: per-k combined bounds check over all 4 d's
// (extremes fold to constants) -> branch-free unrolled fast path.
// ---------------------------------------------------------------------------
#define CORNER(L, qa, qb) { int _s = ((L)>>2)&1; const float4* _p = (const float4*)XS + 2*(L); qa = _p[_s]; qb = _p[_s^1]; }

#define FASTSAMPLE(L, dwq) {                                                          \
    float4 p00a,p00b,p01a,p01b,p10a,p10b,p11a,p11b;                                   \
    CORNER(L,    p00a, p00b);                                                         \
    CORNER((L)+1,  p01a, p01b);                                                       \
    CORNER((L)+46, p10a, p10b);                                                       \
    CORNER((L)+47, p11a, p11b);                                                       \
    float4 dq0 = (dwq)[0], dq1 = (dwq)[1];                                            \
    float v;                                                                          \
    v = w00*p00a.x + w01*p01a.x + w10*p10a.x + w11*p11a.x; acc[0] = fmaf(dq0.x, v, acc[0]); \
    v = w00*p00a.y + w01*p01a.y + w10*p10a.y + w11*p11a.y; acc[1] = fmaf(dq0.y, v, acc[1]); \
    v = w00*p00a.z + w01*p01a.z + w10*p10a.z + w11*p11a.z; acc[2] = fmaf(dq0.z, v, acc[2]); \
    v = w00*p00a.w + w01*p01a.w + w10*p10a.w + w11*p11a.w; acc[3] = fmaf(dq0.w, v, acc[3]); \
    v = w00*p00b.x + w01*p01b.x + w10*p10b.x + w11*p11b.x; acc[4] = fmaf(dq1.x, v, acc[4]); \
    v = w00*p00b.y + w01*p01b.y + w10*p10b.y + w11*p11b.y; acc[5] = fmaf(dq1.y, v, acc[5]); \
    v = w00*p00b.z + w01*p01b.z + w10*p10b.z + w11*p11b.z; acc[6] = fmaf(dq1.z, v, acc[6]); \
    v = w00*p00b.w + w01*p01b.w + w10*p10b.w + w11*p11b.w; acc[7] = fmaf(dq1.w, v, acc[7]); \
}

__global__ __launch_bounds__(256)
void k_deform(const float* __restrict__ x,
              const float* __restrict__ dw2, const float* __restrict__ dw3,
              const float* __restrict__ dw4, const float* __restrict__ dw5)
{
    __shared__ float XS[1012*8];   // [loc = yy*46+xx][ci swizzled]
    __shared__ float DWT[4*9*8];   // [di][k][ci]
    int tid = threadIdx.y*32 + threadIdx.x;
    int b  = blockIdx.z >> 3;
    int c0 = (blockIdx.z & 7) * 8;
    int gy0 = blockIdx.y*8, gx0 = blockIdx.x*32;
    const float* xb = x + (size_t)(b*Cv + c0)*HWv;

    for (int i = tid; i < 8096; i += 256) {
        int ci = i / 1012, loc = i % 1012;
        int yy = loc / 46, xx = loc % 46;
        int gy = gy0 - 7 + yy, gx = gx0 - 7 + xx;
        float v = (gy>=0 && gy<Hv && gx>=0 && gx<Wv) ? xb[(size_t)ci*HWv + gy*Wv + gx] : 0.f;
        XS[loc*8 + (ci ^ (loc & 4))] = v;
    }
    for (int t = tid; t < 288; t += 256) {
        int di = t/72, r = t%72, k = r/8, ci = r%8;
        const float* dp = (di==0)?dw2:(di==1)?dw3:(di==2)?dw4:dw5;
        DWT[t] = dp[(c0+ci)*9 + k];
    }
    __syncthreads();

    int gw = gx0 + threadIdx.x, gh = gy0 + threadIdx.y;
    int pix = gh*Wv + gw;

    float acc[8];
#pragma unroll
    for (int ci = 0; ci < 8; ci++) acc[ci] = 0.f;

    const float* op = g_off + (size_t)b*18*HWv + pix;

#pragma unroll
    for (int k = 0; k < 9; k++) {
        const int ky = k/3 - 1, kx = k%3 - 1;
        float py = op[(size_t)(2*k  )*HWv] + (float)gh;
        float px = op[(size_t)(2*k+1)*HWv] + (float)gw;
        float fy = floorf(py), fx = floorf(px);
        float wy = py - fy, wx = px - fx;
        int y0b = (int)fy, x0b = (int)fx;
        float w11 = wy*wx;
        float w10 = wy - w11;
        float w01 = wx - w11;
        float w00 = 1.f - wy - wx + w11;

        int rely = y0b - gy0 + 7, relx = x0b - gx0 + 7;
        // combined bounds over d=2..5 (ky,kx compile-time per k)
        const int kylo = (ky > 0) ? 2*ky : 5*ky;
        const int kyhi = (ky > 0) ? 5*ky : 2*ky;
        const int kxlo = (kx > 0) ? 2*kx : 5*kx;
        const int kxhi = (kx > 0) ? 5*kx : 2*kx;
        bool allfast = (rely + kylo >= 0) && (rely + kyhi <= 20) &&
                       (relx + kxlo >= 0) && (relx + kxhi <= 44);

        if (allfast) {
#pragma unroll
            for (int di = 0; di < 4; di++) {
                int d = di + 2;
                int L = (rely + d*ky)*46 + (relx + d*kx);
                const float4* dwq = (const float4*)&DWT[(di*9 + k)*8];
                FASTSAMPLE(L, dwq);
            }
        } else {
#pragma unroll
            for (int di = 0; di < 4; di++) {
                int d = di + 2;
                int y0 = y0b + d*ky, x0 = x0b + d*kx;
                int sy = y0 - gy0 + 7, sx = x0 - gx0 + 7;
                const float4* dwq = (const float4*)&DWT[(di*9 + k)*8];
                if (sy >= 0 && sy <= 20 && sx >= 0 && sx <= 44) {
                    int L = sy*46 + sx;
                    FASTSAMPLE(L, dwq);
                } else {
                    int y1 = y0 + 1, x1 = x0 + 1;
                    bool vy0 = (y0>=0)&&(y0<Hv), vy1 = (y1>=0)&&(y1<Hv);
                    bool vx0 = (x0>=0)&&(x0<Wv), vx1 = (x1>=0)&&(x1<Wv);
                    int iy0 = vy0? y0:0, iy1 = vy1? y1:0;
                    int ix0 = vx0? x0:0, ix1 = vx1? x1:0;
                    const float* dwf = (const float*)dwq;
#pragma unroll
                    for (int ci = 0; ci < 8; ci++) {
                        const float* xc = xb + (size_t)ci*HWv;
                        float g00 = (vy0&&vx0)? xc[iy0*Wv+ix0] : 0.f;
                        float g01 = (vy0&&vx1)? xc[iy0*Wv+ix1] : 0.f;
                        float g10 = (vy1&&vx0)? xc[iy1*Wv+ix0] : 0.f;
                        float g11 = (vy1&&vx1)? xc[iy1*Wv+ix1] : 0.f;
                        float v = w00*g00 + w01*g01 + w10*g10 + w11*g11;
                        acc[ci] = fmaf(dwf[ci], v, acc[ci]);
                    }
                }
            }
        }
    }
    float* outp = g_dsum + (size_t)(b*Cv + c0)*HWv + pix;
#pragma unroll
    for (int ci = 0; ci < 8; ci++) outp[(size_t)ci*HWv] = acc[ci];
}

// ---------------------------------------------------------------------------
// Kernel 4: out = bn5(bias(fin_w @ dsum)) * x, tiled GEMM.
// Block = 32 couts x 64 px, 256 threads, thread = 2c x 4px (8 outputs).
// Grid = 1024 blocks -> ~55 warps/SM (R7 was grid-limited at 20.8% occ).
// FW tile transposed with pad-34 (conflict-free scatter, aligned reads).
// ---------------------------------------------------------------------------
__global__ __launch_bounds__(256)
void k_final(const float* __restrict__ x,
             const float* __restrict__ fw, const float* __restrict__ fb,
             const float* __restrict__ s5, const float* __restrict__ b5,
             float* __restrict__ out)
{
    __shared__ float FWs[64*34];   // FWs[cin*34+co] = fw[(cog*32+co)*64+cin]
    __shared__ float DS[64*64];    // DS[cin*64+p]
    int tid = threadIdx.x;
    int b   = blockIdx.z;
    int cog = blockIdx.y;          // cout half: couts cog*32 .. cog*32+31
    int pix0 = blockIdx.x*64;

    // FW half-tile: coalesced gmem read, padded transposed smem write
    const float* fwh = fw + (size_t)cog*32*64;
    for (int i = tid; i < 2048; i += 256) {
        int co = i >> 6, cin = i & 63;
        FWs[cin*34 + co] = fwh[i];
    }
    // DS tile: float4 coalesced
    const float* dp = g_dsum + (size_t)b*Cv*HWv + pix0;
    for (int i = tid; i < 1024; i += 256) {
        int cin = i >> 4, p4 = i & 15;
        ((float4*)DS)[cin*16 + p4] = *(const float4*)(dp + (size_t)cin*HWv + p4*4);
    }
    __syncthreads();

    int tp = tid & 15;        // pixels tp*4 .. tp*4+3
    int tc = tid >> 4;        // local couts tc*2, tc*2+1
    float4 a0 = {0,0,0,0}, a1 = {0,0,0,0};

#pragma unroll 8
    for (int cin = 0; cin < 64; cin++) {
        float4 d = *(const float4*)&DS[cin*64 + tp*4];
        float2 w = *(const float2*)&FWs[cin*34 + tc*2];
        a0.x = fmaf(w.x, d.x, a0.x); a0.y = fmaf(w.x, d.y, a0.y);
        a0.z = fmaf(w.x, d.z, a0.z); a0.w = fmaf(w.x, d.w, a0.w);
        a1.x = fmaf(w.y, d.x, a1.x); a1.y = fmaf(w.y, d.y, a1.y);
        a1.z = fmaf(w.y, d.z, a1.z); a1.w = fmaf(w.y, d.w, a1.w);
    }

    float4 accs[2] = {a0, a1};
#pragma unroll
    for (int i = 0; i < 2; i++) {
        int j = cog*32 + tc*2 + i;
        float sc = s5[j], fbj = fb[j], bbj = b5[j];
        size_t o = (size_t)(b*Cv + j)*HWv + pix0 + tp*4;
        float4 xv = *(const float4*)(x + o);
        float4 r;
        r.x = fmaf(sc, accs[i].x + fbj, bbj) * xv.x;
        r.y = fmaf(sc, accs[i].y + fbj, bbj) * xv.y;
        r.z = fmaf(sc, accs[i].z + fbj, bbj) * xv.z;
        r.w = fmaf(sc, accs[i].w + fbj, bbj) * xv.w;
        *(float4*)(out + o) = r;
    }
}

// ---------------------------------------------------------------------------
extern "C" void kernel_launch(void* const* d_in, const int* in_sizes, int n_in,
                              void* d_out, int out_size)
{
    int ix, i_off1w, i_off1b, i_bn1s, i_bn1b, i_off2w, i_off2b, i_bn2s, i_bn2b,
        i_off3w, i_off3b, i_bn3s, i_bn3b, i_balw, i_balb, i_bn4s, i_bn4b,
        i_dw2, i_dw3, i_dw4, i_dw5, i_finw, i_finb, i_bn5s, i_bn5b;

    if (in_sizes[0] == Bv*Cv*HWv) {
        ix=0;  i_off1w=1;  i_off1b=2;  i_bn1s=3;  i_bn1b=4;
        i_off2w=5;  i_off2b=6;  i_bn2s=7;  i_bn2b=8;
        i_off3w=9;  i_off3b=10; i_bn3s=11; i_bn3b=12;
        i_balw=13; i_balb=14; i_bn4s=15; i_bn4b=16;
        i_dw2=17; i_dw3=18; i_dw4=19; i_dw5=20;
        i_finw=21; i_finb=22; i_bn5s=23; i_bn5b=24;
    } else {
        i_balb=0; i_balw=1; i_bn1b=2; i_bn1s=3; i_bn2b=4; i_bn2s=5;
        i_bn3b=6; i_bn3s=7; i_bn4b=8; i_bn4s=9; i_bn5b=10; i_bn5s=11;
        i_dw2=12; i_dw3=13; i_dw4=14; i_dw5=15;
        i_finb=16; i_finw=17; i_off1b=18; i_off1w=19;
        i_off2b=20; i_off2w=21; i_off3b=22; i_off3w=23; ix=24;
    }

    const float* x      = (const float*)d_in[ix];
    const float* off1_w = (const float*)d_in[i_off1w];
    const float* off1_b = (const float*)d_in[i_off1b];
    const float* bn1_s  = (const float*)d_in[i_bn1s];
    const float* bn1_b  = (const float*)d_in[i_bn1b];
    const float* off2_w = (const float*)d_in[i_off2w];
    const float* off2_b = (const float*)d_in[i_off2b];
    const float* bn2_s  = (const float*)d_in[i_bn2s];
    const float* bn2_b  = (const float*)d_in[i_bn2b];
    const float* off3_w = (const float*)d_in[i_off3w];
    const float* off3_b = (const float*)d_in[i_off3b];
    const float* bn3_s  = (const float*)d_in[i_bn3s];
    const float* bn3_b  = (const float*)d_in[i_bn3b];
    const float* bal_w  = (const float*)d_in[i_balw];
    const float* bal_b  = (const float*)d_in[i_balb];
    const float* bn4_s  = (const float*)d_in[i_bn4s];
    const float* bn4_b  = (const float*)d_in[i_bn4b];
    const float* dw2    = (const float*)d_in[i_dw2];
    const float* dw3    = (const float*)d_in[i_dw3];
    const float* dw4    = (const float*)d_in[i_dw4];
    const float* dw5    = (const float*)d_in[i_dw5];
    const float* fin_w  = (const float*)d_in[i_finw];
    const float* fin_b  = (const float*)d_in[i_finb];
    const float* bn5_s  = (const float*)d_in[i_bn5s];
    const float* bn5_b  = (const float*)d_in[i_bn5b];
    float* out = (float*)d_out;

    dim3 blk(32, 8);
    k_branch<<<dim3(4, 16, Bv*Cv), blk>>>(x,
        off1_w, off1_b, bn1_s, bn1_b,
        off2_w, off2_b, bn2_s, bn2_b,
        off3_w, off3_b, bn3_s, bn3_b);
    k_off<<<dim3(HWv/64, Bv), 64>>>(bal_w, bal_b, bn4_s, bn4_b);
    k_deform<<<dim3(4, 16, Bv*8), blk>>>(x, dw2, dw3, dw4, dw5);
    k_final<<<dim3(HWv/64, 2, Bv), 256>>>(x, fin_w, fin_b, bn5_s, bn5_b, out);
}

// round 10
// speedup vs baseline: 1.5905x; 1.0991x over previous
#include <cuda_runtime.h>
#include <cuda_fp16.h>

#define Bv 2
#define Cv 64
#define Hv 128
#define Wv 128
#define HWv (Hv*Wv)

// Scratch buffers (static __device__ — no runtime allocation)
__device__ float g_s[Bv*Cv*HWv];      // o1+o2+o3 fused branch output
__device__ float g_off[Bv*18*HWv];    // 18 offset channels
__device__ float g_dsum[Bv*Cv*HWv];   // sum of 4 deformable convs

// ---------------------------------------------------------------------------
// Kernel 1: s = bn1(bias(dw 1x15)) + bn2(bias(dw 15x1)) + bn3(bias(dw 3x3))
// ---------------------------------------------------------------------------
__global__ __launch_bounds__(256)
void k_branch(const float* __restrict__ x,
              const float* __restrict__ w1, const float* __restrict__ b1,
              const float* __restrict__ s1, const float* __restrict__ bb1,
              const float* __restrict__ w2, const float* __restrict__ b2,
              const float* __restrict__ s2, const float* __restrict__ bb2,
              const float* __restrict__ w3, const float* __restrict__ b3,
              const float* __restrict__ s3, const float* __restrict__ bb3)
{
    __shared__ float XS[22*46];
    __shared__ float WS[39];
    int tid = threadIdx.y*32 + threadIdx.x;
    int b = blockIdx.z / Cv, c = blockIdx.z % Cv;
    int gy0 = blockIdx.y*8, gx0 = blockIdx.x*32;
    const float* xc = x + (size_t)(b*Cv + c)*HWv;

    for (int i = tid; i < 22*46; i += 256) {
        int yy = i/46, xx = i%46;
        int gy = gy0 - 7 + yy, gx = gx0 - 7 + xx;
        XS[i] = (gy>=0 && gy<Hv && gx>=0 && gx<Wv) ? xc[gy*Wv+gx] : 0.f;
    }
    if (tid < 15)       WS[tid] = w1[c*15 + tid];
    else if (tid < 30)  WS[tid] = w2[c*15 + tid-15];
    else if (tid < 39)  WS[tid] = w3[c*9  + tid-30];
    __syncthreads();

    int tx = threadIdx.x, ty = threadIdx.y;
    float c1 = 0.f, c2 = 0.f, c3 = 0.f;
#pragma unroll
    for (int i = 0; i < 15; i++) c1 = fmaf(WS[i],    XS[(ty+7)*46 + tx + i], c1);
#pragma unroll
    for (int i = 0; i < 15; i++) c2 = fmaf(WS[15+i], XS[(ty+i)*46 + tx + 7], c2);
#pragma unroll
    for (int dy = 0; dy < 3; dy++)
#pragma unroll
        for (int dx = 0; dx < 3; dx++)
            c3 = fmaf(WS[30+dy*3+dx], XS[(ty+6+dy)*46 + tx+6+dx], c3);

    float a1 = s1[c], a2 = s2[c], a3 = s3[c];
    float cst = fmaf(a1, b1[c], bb1[c]) + fmaf(a2, b2[c], bb2[c]) + fmaf(a3, b3[c], bb3[c]);
    g_s[(size_t)(b*Cv+c)*HWv + (gy0+ty)*Wv + gx0+tx] =
        fmaf(a1, c1, fmaf(a2, c2, fmaf(a3, c3, cst)));
}

// ---------------------------------------------------------------------------
// Kernel 2: off = bn4(bias(1x1 conv C->18 of s))
// ---------------------------------------------------------------------------
__global__ __launch_bounds__(64)
void k_off(const float* __restrict__ balw, const float* __restrict__ balb,
           const float* __restrict__ s4,   const float* __restrict__ b4)
{
    __shared__ float BW[64*18];
    int tid = threadIdx.x;
    int b = blockIdx.y;
    int pix = blockIdx.x*64 + tid;
    for (int t = tid; t < 64*18; t += 64) {
        int c = t/18, j = t%18;
        BW[t] = balw[j*64 + c];           // BW[c*18+j]
    }
    __syncthreads();

    float acc[18];
#pragma unroll
    for (int j = 0; j < 18; j++) acc[j] = 0.f;

    const float* sp = g_s + (size_t)b*Cv*HWv + pix;
#pragma unroll 8
    for (int c = 0; c < 64; c++) {
        float v = sp[(size_t)c*HWv];
        const float* bwc = &BW[c*18];
#pragma unroll
        for (int j = 0; j < 18; j++) acc[j] = fmaf(bwc[j], v, acc[j]);
    }
#pragma unroll
    for (int j = 0; j < 18; j++)
        g_off[((size_t)b*18 + j)*HWv + pix] = fmaf(s4[j], acc[j] + balb[j], b4[j]);
}

// ---------------------------------------------------------------------------
// Kernel 3: sum of 4 deformable depthwise convs (d = 2,3,4,5), shared offsets.
// fp16 sample tile: XS[loc*8+ci] as __half — one 16B LDS.128 fetches a corner
// for all 8 channels (halves the smem crossbar traffic vs fp32).
// Bilinear computed in half2, converted to fp32, accumulated in fp32 with
// fp32 depthwise weights. Slow path (rare) stays full-fp32 via global loads.
// ---------------------------------------------------------------------------
__device__ __forceinline__ void bil8h(uint4 a, uint4 b, uint4 c, uint4 d,
                                      __half2 h00, __half2 h01, __half2 h10, __half2 h11,
                                      float4 dq0, float4 dq1, float* acc)
{
    const __half2* pa = (const __half2*)&a;
    const __half2* pb = (const __half2*)&b;
    const __half2* pc = (const __half2*)&c;
    const __half2* pd = (const __half2*)&d;
    float dw[8] = {dq0.x,dq0.y,dq0.z,dq0.w,dq1.x,dq1.y,dq1.z,dq1.w};
#pragma unroll
    for (int j = 0; j < 4; j++) {
        __half2 v = __hmul2(h00, pa[j]);
        v = __hfma2(h01, pb[j], v);
        v = __hfma2(h10, pc[j], v);
        v = __hfma2(h11, pd[j], v);
        float2 vf = __half22float2(v);
        acc[2*j]   = fmaf(dw[2*j],   vf.x, acc[2*j]);
        acc[2*j+1] = fmaf(dw[2*j+1], vf.y, acc[2*j+1]);
    }
}

#define FASTSAMPLE(L, dwq) {                                   \
    uint4 u00 = *(const uint4*)&XS[(L)*8];                     \
    uint4 u01 = *(const uint4*)&XS[((L)+1)*8];                 \
    uint4 u10 = *(const uint4*)&XS[((L)+46)*8];                \
    uint4 u11 = *(const uint4*)&XS[((L)+47)*8];                \
    bil8h(u00,u01,u10,u11, h00,h01,h10,h11, (dwq)[0], (dwq)[1], acc); \
}

__global__ __launch_bounds__(256)
void k_deform(const float* __restrict__ x,
              const float* __restrict__ dw2, const float* __restrict__ dw3,
              const float* __restrict__ dw4, const float* __restrict__ dw5)
{
    __shared__ __half XS[1012*8];  // [loc = yy*46+xx][ci] — 16B per loc
    __shared__ float DWT[4*9*8];   // [di][k][ci]
    int tid = threadIdx.y*32 + threadIdx.x;
    int b  = blockIdx.z >> 3;
    int c0 = (blockIdx.z & 7) * 8;
    int gy0 = blockIdx.y*8, gx0 = blockIdx.x*32;
    const float* xb = x + (size_t)(b*Cv + c0)*HWv;

    for (int i = tid; i < 8096; i += 256) {
        int ci = i / 1012, loc = i % 1012;
        int yy = loc / 46, xx = loc % 46;
        int gy = gy0 - 7 + yy, gx = gx0 - 7 + xx;
        float v = (gy>=0 && gy<Hv && gx>=0 && gx<Wv) ? xb[(size_t)ci*HWv + gy*Wv + gx] : 0.f;
        XS[loc*8 + ci] = __float2half(v);
    }
    for (int t = tid; t < 288; t += 256) {
        int di = t/72, r = t%72, k = r/8, ci = r%8;
        const float* dp = (di==0)?dw2:(di==1)?dw3:(di==2)?dw4:dw5;
        DWT[t] = dp[(c0+ci)*9 + k];
    }
    __syncthreads();

    int gw = gx0 + threadIdx.x, gh = gy0 + threadIdx.y;
    int pix = gh*Wv + gw;

    float acc[8];
#pragma unroll
    for (int ci = 0; ci < 8; ci++) acc[ci] = 0.f;

    const float* op = g_off + (size_t)b*18*HWv + pix;

#pragma unroll
    for (int k = 0; k < 9; k++) {
        const int ky = k/3 - 1, kx = k%3 - 1;
        float py = op[(size_t)(2*k  )*HWv] + (float)gh;
        float px = op[(size_t)(2*k+1)*HWv] + (float)gw;
        float fy = floorf(py), fx = floorf(px);
        float wy = py - fy, wx = px - fx;
        int y0b = (int)fy, x0b = (int)fx;
        float w11 = wy*wx;
        float w10 = wy - w11;
        float w01 = wx - w11;
        float w00 = 1.f - wy - wx + w11;
        __half2 h00 = __float2half2_rn(w00);
        __half2 h01 = __float2half2_rn(w01);
        __half2 h10 = __float2half2_rn(w10);
        __half2 h11 = __float2half2_rn(w11);

        int rely = y0b - gy0 + 7, relx = x0b - gx0 + 7;
        // combined bounds over d=2..5 (ky,kx compile-time per k)
        const int kylo = (ky > 0) ? 2*ky : 5*ky;
        const int kyhi = (ky > 0) ? 5*ky : 2*ky;
        const int kxlo = (kx > 0) ? 2*kx : 5*kx;
        const int kxhi = (kx > 0) ? 5*kx : 2*kx;
        bool allfast = (rely + kylo >= 0) && (rely + kyhi <= 20) &&
                       (relx + kxlo >= 0) && (relx + kxhi <= 44);

        if (allfast) {
#pragma unroll
            for (int di = 0; di < 4; di++) {
                int d = di + 2;
                int L = (rely + d*ky)*46 + (relx + d*kx);
                const float4* dwq = (const float4*)&DWT[(di*9 + k)*8];
                FASTSAMPLE(L, dwq);
            }
        } else {
#pragma unroll
            for (int di = 0; di < 4; di++) {
                int d = di + 2;
                int y0 = y0b + d*ky, x0 = x0b + d*kx;
                int sy = y0 - gy0 + 7, sx = x0 - gx0 + 7;
                const float4* dwq = (const float4*)&DWT[(di*9 + k)*8];
                if (sy >= 0 && sy <= 20 && sx >= 0 && sx <= 44) {
                    int L = sy*46 + sx;
                    FASTSAMPLE(L, dwq);
                } else {
                    int y1 = y0 + 1, x1 = x0 + 1;
                    bool vy0 = (y0>=0)&&(y0<Hv), vy1 = (y1>=0)&&(y1<Hv);
                    bool vx0 = (x0>=0)&&(x0<Wv), vx1 = (x1>=0)&&(x1<Wv);
                    int iy0 = vy0? y0:0, iy1 = vy1? y1:0;
                    int ix0 = vx0? x0:0, ix1 = vx1? x1:0;
                    const float* dwf = (const float*)dwq;
#pragma unroll
                    for (int ci = 0; ci < 8; ci++) {
                        const float* xc = xb + (size_t)ci*HWv;
                        float g00 = (vy0&&vx0)? xc[iy0*Wv+ix0] : 0.f;
                        float g01 = (vy0&&vx1)? xc[iy0*Wv+ix1] : 0.f;
                        float g10 = (vy1&&vx0)? xc[iy1*Wv+ix0] : 0.f;
                        float g11 = (vy1&&vx1)? xc[iy1*Wv+ix1] : 0.f;
                        float v = w00*g00 + w01*g01 + w10*g10 + w11*g11;
                        acc[ci] = fmaf(dwf[ci], v, acc[ci]);
                    }
                }
            }
        }
    }
    float* outp = g_dsum + (size_t)(b*Cv + c0)*HWv + pix;
#pragma unroll
    for (int ci = 0; ci < 8; ci++) outp[(size_t)ci*HWv] = acc[ci];
}

// ---------------------------------------------------------------------------
// Kernel 4: out = bn5(bias(fin_w @ dsum)) * x, tiled GEMM.
// Block = 64 couts x 64 px, 256 threads, thread = 4c x 4px (16 outputs):
// 2 LDS.128 per 16 FMA = 2 B/FMA (was 3 — kernel is smem-crossbar bound).
// FW transposed with pad-68 (aligned float4 reads, mostly broadcast).
// ---------------------------------------------------------------------------
__global__ __launch_bounds__(256)
void k_final(const float* __restrict__ x,
             const float* __restrict__ fw, const float* __restrict__ fb,
             const float* __restrict__ s5, const float* __restrict__ b5,
             float* __restrict__ out)
{
    __shared__ float FWs[64*68];   // FWs[cin*68+co] = fw[co*64+cin]
    __shared__ float DS[64*64];    // DS[cin*64+p]
    int tid = threadIdx.x;
    int b   = blockIdx.y;
    int pix0 = blockIdx.x*64;

    for (int i = tid; i < 4096; i += 256) {
        int co = i >> 6, cin = i & 63;
        FWs[cin*68 + co] = fw[i];
    }
    const float* dp = g_dsum + (size_t)b*Cv*HWv + pix0;
    for (int i = tid; i < 1024; i += 256) {
        int cin = i >> 4, p4 = i & 15;
        ((float4*)DS)[cin*16 + p4] = *(const float4*)(dp + (size_t)cin*HWv + p4*4);
    }
    __syncthreads();

    int tp = tid & 15;        // pixels tp*4 .. tp*4+3
    int tc = tid >> 4;        // couts  tc*4 .. tc*4+3
    float4 a0 = {0,0,0,0}, a1 = {0,0,0,0}, a2 = {0,0,0,0}, a3 = {0,0,0,0};

#pragma unroll 4
    for (int cin = 0; cin < 64; cin++) {
        float4 d = *(const float4*)&DS [cin*64 + tp*4];
        float4 w = *(const float4*)&FWs[cin*68 + tc*4];
        a0.x = fmaf(w.x, d.x, a0.x); a0.y = fmaf(w.x, d.y, a0.y);
        a0.z = fmaf(w.x, d.z, a0.z); a0.w = fmaf(w.x, d.w, a0.w);
        a1.x = fmaf(w.y, d.x, a1.x); a1.y = fmaf(w.y, d.y, a1.y);
        a1.z = fmaf(w.y, d.z, a1.z); a1.w = fmaf(w.y, d.w, a1.w);
        a2.x = fmaf(w.z, d.x, a2.x); a2.y = fmaf(w.z, d.y, a2.y);
        a2.z = fmaf(w.z, d.z, a2.z); a2.w = fmaf(w.z, d.w, a2.w);
        a3.x = fmaf(w.w, d.x, a3.x); a3.y = fmaf(w.w, d.y, a3.y);
        a3.z = fmaf(w.w, d.z, a3.z); a3.w = fmaf(w.w, d.w, a3.w);
    }

    float4 accs[4] = {a0, a1, a2, a3};
#pragma unroll
    for (int i = 0; i < 4; i++) {
        int j = tc*4 + i;
        float sc = s5[j], fbj = fb[j], bbj = b5[j];
        size_t o = (size_t)(b*Cv + j)*HWv + pix0 + tp*4;
        float4 xv = *(const float4*)(x + o);
        float4 r;
        r.x = fmaf(sc, accs[i].x + fbj, bbj) * xv.x;
        r.y = fmaf(sc, accs[i].y + fbj, bbj) * xv.y;
        r.z = fmaf(sc, accs[i].z + fbj, bbj) * xv.z;
        r.w = fmaf(sc, accs[i].w + fbj, bbj) * xv.w;
        *(float4*)(out + o) = r;
    }
}

// ---------------------------------------------------------------------------
extern "C" void kernel_launch(void* const* d_in, const int* in_sizes, int n_in,
                              void* d_out, int out_size)
{
    int ix, i_off1w, i_off1b, i_bn1s, i_bn1b, i_off2w, i_off2b, i_bn2s, i_bn2b,
        i_off3w, i_off3b, i_bn3s, i_bn3b, i_balw, i_balb, i_bn4s, i_bn4b,
        i_dw2, i_dw3, i_dw4, i_dw5, i_finw, i_finb, i_bn5s, i_bn5b;

    if (in_sizes[0] == Bv*Cv*HWv) {
        ix=0;  i_off1w=1;  i_off1b=2;  i_bn1s=3;  i_bn1b=4;
        i_off2w=5;  i_off2b=6;  i_bn2s=7;  i_bn2b=8;
        i_off3w=9;  i_off3b=10; i_bn3s=11; i_bn3b=12;
        i_balw=13; i_balb=14; i_bn4s=15; i_bn4b=16;
        i_dw2=17; i_dw3=18; i_dw4=19; i_dw5=20;
        i_finw=21; i_finb=22; i_bn5s=23; i_bn5b=24;
    } else {
        i_balb=0; i_balw=1; i_bn1b=2; i_bn1s=3; i_bn2b=4; i_bn2s=5;
        i_bn3b=6; i_bn3s=7; i_bn4b=8; i_bn4s=9; i_bn5b=10; i_bn5s=11;
        i_dw2=12; i_dw3=13; i_dw4=14; i_dw5=15;
        i_finb=16; i_finw=17; i_off1b=18; i_off1w=19;
        i_off2b=20; i_off2w=21; i_off3b=22; i_off3w=23; ix=24;
    }

    const float* x      = (const float*)d_in[ix];
    const float* off1_w = (const float*)d_in[i_off1w];
    const float* off1_b = (const float*)d_in[i_off1b];
    const float* bn1_s  = (const float*)d_in[i_bn1s];
    const float* bn1_b  = (const float*)d_in[i_bn1b];
    const float* off2_w = (const float*)d_in[i_off2w];
    const float* off2_b = (const float*)d_in[i_off2b];
    const float* bn2_s  = (const float*)d_in[i_bn2s];
    const float* bn2_b  = (const float*)d_in[i_bn2b];
    const float* off3_w = (const float*)d_in[i_off3w];
    const float* off3_b = (const float*)d_in[i_off3b];
    const float* bn3_s  = (const float*)d_in[i_bn3s];
    const float* bn3_b  = (const float*)d_in[i_bn3b];
    const float* bal_w  = (const float*)d_in[i_balw];
    const float* bal_b  = (const float*)d_in[i_balb];
    const float* bn4_s  = (const float*)d_in[i_bn4s];
    const float* bn4_b  = (const float*)d_in[i_bn4b];
    const float* dw2    = (const float*)d_in[i_dw2];
    const float* dw3    = (const float*)d_in[i_dw3];
    const float* dw4    = (const float*)d_in[i_dw4];
    const float* dw5    = (const float*)d_in[i_dw5];
    const float* fin_w  = (const float*)d_in[i_finw];
    const float* fin_b  = (const float*)d_in[i_finb];
    const float* bn5_s  = (const float*)d_in[i_bn5s];
    const float* bn5_b  = (const float*)d_in[i_bn5b];
    float* out = (float*)d_out;

    dim3 blk(32, 8);
    k_branch<<<dim3(4, 16, Bv*Cv), blk>>>(x,
        off1_w, off1_b, bn1_s, bn1_b,
        off2_w, off2_b, bn2_s, bn2_b,
        off3_w, off3_b, bn3_s, bn3_b);
    k_off<<<dim3(HWv/64, Bv), 64>>>(bal_w, bal_b, bn4_s, bn4_b);
    k_deform<<<dim3(4, 16, Bv*8), blk>>>(x, dw2, dw3, dw4, dw5);
    k_final<<<dim3(HWv/64, Bv), 256>>>(x, fin_w, fin_b, bn5_s, bn5_b, out);
}

// round 12
// speedup vs baseline: 1.7745x; 1.1156x over previous
#include <cuda_runtime.h>
#include <cuda_fp16.h>

#define Bv 2
#define Cv 64
#define Hv 128
#define Wv 128
#define HWv (Hv*Wv)

// Scratch buffers (static __device__ — no runtime allocation)
__device__ float  g_s[Bv*Cv*HWv];      // o1+o2+o3 fused branch output
__device__ float  g_off[Bv*18*HWv];    // 18 offset channels
__device__ __half g_dsum[Bv*Cv*HWv];   // sum of 4 deformable convs (fp16)

// ---------------------------------------------------------------------------
// Kernel 1: s = bn1(bias(dw 1x15)) + bn2(bias(dw 15x1)) + bn3(bias(dw 3x3))
// ---------------------------------------------------------------------------
__global__ __launch_bounds__(256)
void k_branch(const float* __restrict__ x,
              const float* __restrict__ w1, const float* __restrict__ b1,
              const float* __restrict__ s1, const float* __restrict__ bb1,
              const float* __restrict__ w2, const float* __restrict__ b2,
              const float* __restrict__ s2, const float* __restrict__ bb2,
              const float* __restrict__ w3, const float* __restrict__ b3,
              const float* __restrict__ s3, const float* __restrict__ bb3)
{
    __shared__ float XS[22*46];
    __shared__ float WS[39];
    int tid = threadIdx.y*32 + threadIdx.x;
    int b = blockIdx.z / Cv, c = blockIdx.z % Cv;
    int gy0 = blockIdx.y*8, gx0 = blockIdx.x*32;
    const float* xc = x + (size_t)(b*Cv + c)*HWv;

    for (int i = tid; i < 22*46; i += 256) {
        int yy = i/46, xx = i%46;
        int gy = gy0 - 7 + yy, gx = gx0 - 7 + xx;
        XS[i] = (gy>=0 && gy<Hv && gx>=0 && gx<Wv) ? xc[gy*Wv+gx] : 0.f;
    }
    if (tid < 15)       WS[tid] = w1[c*15 + tid];
    else if (tid < 30)  WS[tid] = w2[c*15 + tid-15];
    else if (tid < 39)  WS[tid] = w3[c*9  + tid-30];
    __syncthreads();

    int tx = threadIdx.x, ty = threadIdx.y;
    float c1 = 0.f, c2 = 0.f, c3 = 0.f;
#pragma unroll
    for (int i = 0; i < 15; i++) c1 = fmaf(WS[i],    XS[(ty+7)*46 + tx + i], c1);
#pragma unroll
    for (int i = 0; i < 15; i++) c2 = fmaf(WS[15+i], XS[(ty+i)*46 + tx + 7], c2);
#pragma unroll
    for (int dy = 0; dy < 3; dy++)
#pragma unroll
        for (int dx = 0; dx < 3; dx++)
            c3 = fmaf(WS[30+dy*3+dx], XS[(ty+6+dy)*46 + tx+6+dx], c3);

    float a1 = s1[c], a2 = s2[c], a3 = s3[c];
    float cst = fmaf(a1, b1[c], bb1[c]) + fmaf(a2, b2[c], bb2[c]) + fmaf(a3, b3[c], bb3[c]);
    g_s[(size_t)(b*Cv+c)*HWv + (gy0+ty)*Wv + gx0+tx] =
        fmaf(a1, c1, fmaf(a2, c2, fmaf(a3, c3, cst)));
}

// ---------------------------------------------------------------------------
// Kernel 2: off = bn4(bias(1x1 conv C->18 of s))
// ---------------------------------------------------------------------------
__global__ __launch_bounds__(64)
void k_off(const float* __restrict__ balw, const float* __restrict__ balb,
           const float* __restrict__ s4,   const float* __restrict__ b4)
{
    __shared__ float BW[64*18];
    int tid = threadIdx.x;
    int b = blockIdx.y;
    int pix = blockIdx.x*64 + tid;
    for (int t = tid; t < 64*18; t += 64) {
        int c = t/18, j = t%18;
        BW[t] = balw[j*64 + c];           // BW[c*18+j]
    }
    __syncthreads();

    float acc[18];
#pragma unroll
    for (int j = 0; j < 18; j++) acc[j] = 0.f;

    const float* sp = g_s + (size_t)b*Cv*HWv + pix;
#pragma unroll 8
    for (int c = 0; c < 64; c++) {
        float v = sp[(size_t)c*HWv];
        const float* bwc = &BW[c*18];
#pragma unroll
        for (int j = 0; j < 18; j++) acc[j] = fmaf(bwc[j], v, acc[j]);
    }
#pragma unroll
    for (int j = 0; j < 18; j++)
        g_off[((size_t)b*18 + j)*HWv + pix] = fmaf(s4[j], acc[j] + balb[j], b4[j]);
}

// ---------------------------------------------------------------------------
// Kernel 3: sum of 4 deformable depthwise convs (d = 2,3,4,5), shared offsets.
// fp16 sample tile; bilinear in half2, fp32 accumulate; fp16 dsum store.
// ---------------------------------------------------------------------------
__device__ __forceinline__ void bil8h(uint4 a, uint4 b, uint4 c, uint4 d,
                                      __half2 h00, __half2 h01, __half2 h10, __half2 h11,
                                      float4 dq0, float4 dq1, float* acc)
{
    const __half2* pa = (const __half2*)&a;
    const __half2* pb = (const __half2*)&b;
    const __half2* pc = (const __half2*)&c;
    const __half2* pd = (const __half2*)&d;
    float dw[8] = {dq0.x,dq0.y,dq0.z,dq0.w,dq1.x,dq1.y,dq1.z,dq1.w};
#pragma unroll
    for (int j = 0; j < 4; j++) {
        __half2 v = __hmul2(h00, pa[j]);
        v = __hfma2(h01, pb[j], v);
        v = __hfma2(h10, pc[j], v);
        v = __hfma2(h11, pd[j], v);
        float2 vf = __half22float2(v);
        acc[2*j]   = fmaf(dw[2*j],   vf.x, acc[2*j]);
        acc[2*j+1] = fmaf(dw[2*j+1], vf.y, acc[2*j+1]);
    }
}

#define FASTSAMPLE(L, dwq) {                                   \
    uint4 u00 = *(const uint4*)&XS[(L)*8];                     \
    uint4 u01 = *(const uint4*)&XS[((L)+1)*8];                 \
    uint4 u10 = *(const uint4*)&XS[((L)+46)*8];                \
    uint4 u11 = *(const uint4*)&XS[((L)+47)*8];                \
    bil8h(u00,u01,u10,u11, h00,h01,h10,h11, (dwq)[0], (dwq)[1], acc); \
}

__global__ __launch_bounds__(256)
void k_deform(const float* __restrict__ x,
              const float* __restrict__ dw2, const float* __restrict__ dw3,
              const float* __restrict__ dw4, const float* __restrict__ dw5)
{
    __shared__ __half XS[1012*8];  // [loc = yy*46+xx][ci] — 16B per loc
    __shared__ float DWT[4*9*8];   // [di][k][ci]
    int tid = threadIdx.y*32 + threadIdx.x;
    int b  = blockIdx.z >> 3;
    int c0 = (blockIdx.z & 7) * 8;
    int gy0 = blockIdx.y*8, gx0 = blockIdx.x*32;
    const float* xb = x + (size_t)(b*Cv + c0)*HWv;

    for (int i = tid; i < 8096; i += 256) {
        int ci = i / 1012, loc = i % 1012;
        int yy = loc / 46, xx = loc % 46;
        int gy = gy0 - 7 + yy, gx = gx0 - 7 + xx;
        float v = (gy>=0 && gy<Hv && gx>=0 && gx<Wv) ? xb[(size_t)ci*HWv + gy*Wv + gx] : 0.f;
        XS[loc*8 + ci] = __float2half(v);
    }
    for (int t = tid; t < 288; t += 256) {
        int di = t/72, r = t%72, k = r/8, ci = r%8;
        const float* dp = (di==0)?dw2:(di==1)?dw3:(di==2)?dw4:dw5;
        DWT[t] = dp[(c0+ci)*9 + k];
    }
    __syncthreads();

    int gw = gx0 + threadIdx.x, gh = gy0 + threadIdx.y;
    int pix = gh*Wv + gw;

    float acc[8];
#pragma unroll
    for (int ci = 0; ci < 8; ci++) acc[ci] = 0.f;

    const float* op = g_off + (size_t)b*18*HWv + pix;

#pragma unroll
    for (int k = 0; k < 9; k++) {
        const int ky = k/3 - 1, kx = k%3 - 1;
        float py = op[(size_t)(2*k  )*HWv] + (float)gh;
        float px = op[(size_t)(2*k+1)*HWv] + (float)gw;
        float fy = floorf(py), fx = floorf(px);
        float wy = py - fy, wx = px - fx;
        int y0b = (int)fy, x0b = (int)fx;
        float w11 = wy*wx;
        float w10 = wy - w11;
        float w01 = wx - w11;
        float w00 = 1.f - wy - wx + w11;
        __half2 h00 = __float2half2_rn(w00);
        __half2 h01 = __float2half2_rn(w01);
        __half2 h10 = __float2half2_rn(w10);
        __half2 h11 = __float2half2_rn(w11);

        int rely = y0b - gy0 + 7, relx = x0b - gx0 + 7;
        const int kylo = (ky > 0) ? 2*ky : 5*ky;
        const int kyhi = (ky > 0) ? 5*ky : 2*ky;
        const int kxlo = (kx > 0) ? 2*kx : 5*kx;
        const int kxhi = (kx > 0) ? 5*kx : 2*kx;
        bool allfast = (rely + kylo >= 0) && (rely + kyhi <= 20) &&
                       (relx + kxlo >= 0) && (relx + kxhi <= 44);

        if (allfast) {
#pragma unroll
            for (int di = 0; di < 4; di++) {
                int d = di + 2;
                int L = (rely + d*ky)*46 + (relx + d*kx);
                const float4* dwq = (const float4*)&DWT[(di*9 + k)*8];
                FASTSAMPLE(L, dwq);
            }
        } else {
#pragma unroll
            for (int di = 0; di < 4; di++) {
                int d = di + 2;
                int y0 = y0b + d*ky, x0 = x0b + d*kx;
                int sy = y0 - gy0 + 7, sx = x0 - gx0 + 7;
                const float4* dwq = (const float4*)&DWT[(di*9 + k)*8];
                if (sy >= 0 && sy <= 20 && sx >= 0 && sx <= 44) {
                    int L = sy*46 + sx;
                    FASTSAMPLE(L, dwq);
                } else {
                    int y1 = y0 + 1, x1 = x0 + 1;
                    bool vy0 = (y0>=0)&&(y0<Hv), vy1 = (y1>=0)&&(y1<Hv);
                    bool vx0 = (x0>=0)&&(x0<Wv), vx1 = (x1>=0)&&(x1<Wv);
                    int iy0 = vy0? y0:0, iy1 = vy1? y1:0;
                    int ix0 = vx0? x0:0, ix1 = vx1? x1:0;
                    const float* dwf = (const float*)dwq;
#pragma unroll
                    for (int ci = 0; ci < 8; ci++) {
                        const float* xc = xb + (size_t)ci*HWv;
                        float g00 = (vy0&&vx0)? xc[iy0*Wv+ix0] : 0.f;
                        float g01 = (vy0&&vx1)? xc[iy0*Wv+ix1] : 0.f;
                        float g10 = (vy1&&vx0)? xc[iy1*Wv+ix0] : 0.f;
                        float g11 = (vy1&&vx1)? xc[iy1*Wv+ix1] : 0.f;
                        float v = w00*g00 + w01*g01 + w10*g10 + w11*g11;
                        acc[ci] = fmaf(dwf[ci], v, acc[ci]);
                    }
                }
            }
        }
    }
    __half* outp = g_dsum + (size_t)(b*Cv + c0)*HWv + pix;
#pragma unroll
    for (int ci = 0; ci < 8; ci++) outp[(size_t)ci*HWv] = __float2half(acc[ci]);
}

// ---------------------------------------------------------------------------
// Kernel 4: out = bn5(bias(fin_w @ dsum)) * x, tiled GEMM (R9 shape: best).
// Block = 32 couts x 64 px, 256 threads, thread = 2c x 4px, grid 1024.
// fp16 dsum converted to fp32 during SMEM fill; inner loop identical to R9.
// ---------------------------------------------------------------------------
__global__ __launch_bounds__(256)
void k_final(const float* __restrict__ x,
             const float* __restrict__ fw, const float* __restrict__ fb,
             const float* __restrict__ s5, const float* __restrict__ b5,
             float* __restrict__ out)
{
    __shared__ float FWs[64*34];   // FWs[cin*34+co] = fw[(cog*32+co)*64+cin]
    __shared__ float DS[64*64];    // DS[cin*64+p]
    int tid = threadIdx.x;
    int b   = blockIdx.z;
    int cog = blockIdx.y;          // cout half: couts cog*32 .. cog*32+31
    int pix0 = blockIdx.x*64;

    const float* fwh = fw + (size_t)cog*32*64;
    for (int i = tid; i < 2048; i += 256) {
        int co = i >> 6, cin = i & 63;
        FWs[cin*34 + co] = fwh[i];
    }
    const __half* dp = g_dsum + (size_t)b*Cv*HWv + pix0;
    for (int i = tid; i < 1024; i += 256) {
        int cin = i >> 4, p4 = i & 15;
        uint2 u = *(const uint2*)(dp + (size_t)cin*HWv + p4*4);   // 4 halves
        float2 f0 = __half22float2(*(const __half2*)&u.x);
        float2 f1 = __half22float2(*(const __half2*)&u.y);
        ((float4*)DS)[cin*16 + p4] = make_float4(f0.x, f0.y, f1.x, f1.y);
    }
    __syncthreads();

    int tp = tid & 15;        // pixels tp*4 .. tp*4+3
    int tc = tid >> 4;        // local couts tc*2, tc*2+1
    float4 a0 = {0,0,0,0}, a1 = {0,0,0,0};

#pragma unroll 8
    for (int cin = 0; cin < 64; cin++) {
        float4 d = *(const float4*)&DS[cin*64 + tp*4];
        float2 w = *(const float2*)&FWs[cin*34 + tc*2];
        a0.x = fmaf(w.x, d.x, a0.x); a0.y = fmaf(w.x, d.y, a0.y);
        a0.z = fmaf(w.x, d.z, a0.z); a0.w = fmaf(w.x, d.w, a0.w);
        a1.x = fmaf(w.y, d.x, a1.x); a1.y = fmaf(w.y, d.y, a1.y);
        a1.z = fmaf(w.y, d.z, a1.z); a1.w = fmaf(w.y, d.w, a1.w);
    }

    float4 accs[2] = {a0, a1};
#pragma unroll
    for (int i = 0; i < 2; i++) {
        int j = cog*32 + tc*2 + i;
        float sc = s5[j], fbj = fb[j], bbj = b5[j];
        size_t o = (size_t)(b*Cv + j)*HWv + pix0 + tp*4;
        float4 xv = *(const float4*)(x + o);
        float4 r;
        r.x = fmaf(sc, accs[i].x + fbj, bbj) * xv.x;
        r.y = fmaf(sc, accs[i].y + fbj, bbj) * xv.y;
        r.z = fmaf(sc, accs[i].z + fbj, bbj) * xv.z;
        r.w = fmaf(sc, accs[i].w + fbj, bbj) * xv.w;
        *(float4*)(out + o) = r;
    }
}

// ---------------------------------------------------------------------------
extern "C" void kernel_launch(void* const* d_in, const int* in_sizes, int n_in,
                              void* d_out, int out_size)
{
    int ix, i_off1w, i_off1b, i_bn1s, i_bn1b, i_off2w, i_off2b, i_bn2s, i_bn2b,
        i_off3w, i_off3b, i_bn3s, i_bn3b, i_balw, i_balb, i_bn4s, i_bn4b,
        i_dw2, i_dw3, i_dw4, i_dw5, i_finw, i_finb, i_bn5s, i_bn5b;

    if (in_sizes[0] == Bv*Cv*HWv) {
        ix=0;  i_off1w=1;  i_off1b=2;  i_bn1s=3;  i_bn1b=4;
        i_off2w=5;  i_off2b=6;  i_bn2s=7;  i_bn2b=8;
        i_off3w=9;  i_off3b=10; i_bn3s=11; i_bn3b=12;
        i_balw=13; i_balb=14; i_bn4s=15; i_bn4b=16;
        i_dw2=17; i_dw3=18; i_dw4=19; i_dw5=20;
        i_finw=21; i_finb=22; i_bn5s=23; i_bn5b=24;
    } else {
        i_balb=0; i_balw=1; i_bn1b=2; i_bn1s=3; i_bn2b=4; i_bn2s=5;
        i_bn3b=6; i_bn3s=7; i_bn4b=8; i_bn4s=9; i_bn5b=10; i_bn5s=11;
        i_dw2=12; i_dw3=13; i_dw4=14; i_dw5=15;
        i_finb=16; i_finw=17; i_off1b=18; i_off1w=19;
        i_off2b=20; i_off2w=21; i_off3b=22; i_off3w=23; ix=24;
    }

    const float* x      = (const float*)d_in[ix];
    const float* off1_w = (const float*)d_in[i_off1w];
    const float* off1_b = (const float*)d_in[i_off1b];
    const float* bn1_s  = (const float*)d_in[i_bn1s];
    const float* bn1_b  = (const float*)d_in[i_bn1b];
    const float* off2_w = (const float*)d_in[i_off2w];
    const float* off2_b = (const float*)d_in[i_off2b];
    const float* bn2_s  = (const float*)d_in[i_bn2s];
    const float* bn2_b  = (const float*)d_in[i_bn2b];
    const float* off3_w = (const float*)d_in[i_off3w];
    const float* off3_b = (const float*)d_in[i_off3b];
    const float* bn3_s  = (const float*)d_in[i_bn3s];
    const float* bn3_b  = (const float*)d_in[i_bn3b];
    const float* bal_w  = (const float*)d_in[i_balw];
    const float* bal_b  = (const float*)d_in[i_balb];
    const float* bn4_s  = (const float*)d_in[i_bn4s];
    const float* bn4_b  = (const float*)d_in[i_bn4b];
    const float* dw2    = (const float*)d_in[i_dw2];
    const float* dw3    = (const float*)d_in[i_dw3];
    const float* dw4    = (const float*)d_in[i_dw4];
    const float* dw5    = (const float*)d_in[i_dw5];
    const float* fin_w  = (const float*)d_in[i_finw];
    const float* fin_b  = (const float*)d_in[i_finb];
    const float* bn5_s  = (const float*)d_in[i_bn5s];
    const float* bn5_b  = (const float*)d_in[i_bn5b];
    float* out = (float*)d_out;

    dim3 blk(32, 8);
    k_branch<<<dim3(4, 16, Bv*Cv), blk>>>(x,
        off1_w, off1_b, bn1_s, bn1_b,
        off2_w, off2_b, bn2_s, bn2_b,
        off3_w, off3_b, bn3_s, bn3_b);
    k_off<<<dim3(HWv/64, Bv), 64>>>(bal_w, bal_b, bn4_s, bn4_b);
    k_deform<<<dim3(4, 16, Bv*8), blk>>>(x, dw2, dw3, dw4, dw5);
    k_final<<<dim3(HWv/64, 2, Bv), 256>>>(x, fin_w, fin_b, bn5_s, bn5_b, out);
}

// round 13
// speedup vs baseline: 1.9120x; 1.0775x over previous
#include <cuda_runtime.h>
#include <cuda_fp16.h>

#define Bv 2
#define Cv 64
#define Hv 128
#define Wv 128
#define HWv (Hv*Wv)

// Scratch buffers (static __device__ — no runtime allocation)
__device__ __half g_s[Bv*Cv*HWv];      // o1+o2+o3 fused branch output (fp16)
__device__ float  g_off[Bv*18*HWv];    // 18 offset channels
__device__ __half g_dsum[Bv*Cv*HWv];   // sum of 4 deformable convs (fp16)

// ---------------------------------------------------------------------------
// Kernel 1: s = bn1(bias(dw 1x15)) + bn2(bias(dw 15x1)) + bn3(bias(dw 3x3))
// Full-width tile (144-pad x 22 rows), thread computes 4 consecutive pixels:
// c1 shares a 20-float register window; c2/c3 use aligned float4 LDS.
// ---------------------------------------------------------------------------
__global__ __launch_bounds__(256)
void k_branch(const float* __restrict__ x,
              const float* __restrict__ w1, const float* __restrict__ b1,
              const float* __restrict__ s1, const float* __restrict__ bb1,
              const float* __restrict__ w2, const float* __restrict__ b2,
              const float* __restrict__ s2, const float* __restrict__ bb2,
              const float* __restrict__ w3, const float* __restrict__ b3,
              const float* __restrict__ s3, const float* __restrict__ bb3)
{
    __shared__ float XS[22*144];   // rows gy0-7..gy0+14, cols gx -7..136 (pad)
    __shared__ float WS[39];
    int tid = threadIdx.y*32 + threadIdx.x;
    int b = blockIdx.z / Cv, c = blockIdx.z % Cv;
    int gy0 = blockIdx.y*8;
    const float* xc = x + (size_t)(b*Cv + c)*HWv;

    for (int i = tid; i < 22*144; i += 256) {
        int yy = i / 144, xx = i - yy*144;
        int gy = gy0 - 7 + yy, gx = xx - 7;
        XS[i] = (gy>=0 && gy<Hv && gx>=0 && gx<Wv) ? xc[gy*Wv+gx] : 0.f;
    }
    if (tid < 15)       WS[tid] = w1[c*15 + tid];
    else if (tid < 30)  WS[tid] = w2[c*15 + tid-15];
    else if (tid < 39)  WS[tid] = w3[c*9  + tid-30];
    __syncthreads();

    int tx = threadIdx.x, ty = threadIdx.y;
    int p0 = tx*4;                 // pixel cols p0..p0+3 (gx = col)

    // c1: 1x15 row conv at halo row ty+7, taps xx = P + i (P = p0+j)
    float c1v[4] = {0,0,0,0};
    {
        const float* row = &XS[(ty+7)*144 + p0];
        float r[20];
#pragma unroll
        for (int q = 0; q < 5; q++) *(float4*)&r[q*4] = *(const float4*)&row[q*4];
#pragma unroll
        for (int i = 0; i < 15; i++) {
            float w = WS[i];
            c1v[0] = fmaf(w, r[i],   c1v[0]);
            c1v[1] = fmaf(w, r[i+1], c1v[1]);
            c1v[2] = fmaf(w, r[i+2], c1v[2]);
            c1v[3] = fmaf(w, r[i+3], c1v[3]);
        }
    }

    // c2: 15x1 col conv, taps (ty+i, xx = P+7) -> cols p0+7..p0+10
    float c2v[4] = {0,0,0,0};
#pragma unroll
    for (int i = 0; i < 15; i++) {
        const float* rw = &XS[(ty+i)*144 + p0 + 4];
        float4 a  = *(const float4*)rw;        // cols p0+4..7
        float4 bq = *(const float4*)(rw + 4);  // cols p0+8..11
        float w = WS[15+i];
        c2v[0] = fmaf(w, a.w,  c2v[0]);
        c2v[1] = fmaf(w, bq.x, c2v[1]);
        c2v[2] = fmaf(w, bq.y, c2v[2]);
        c2v[3] = fmaf(w, bq.z, c2v[3]);
    }

    // c3: 3x3, taps (ty+6+dy, xx = P+6+dx) -> cols p0+6..p0+11
    float c3v[4] = {0,0,0,0};
#pragma unroll
    for (int dy = 0; dy < 3; dy++) {
        const float* rw = &XS[(ty+6+dy)*144 + p0 + 4];
        float t[8];
        *(float4*)&t[0] = *(const float4*)rw;       // cols p0+4..7
        *(float4*)&t[4] = *(const float4*)(rw + 4); // cols p0+8..11
#pragma unroll
        for (int dx = 0; dx < 3; dx++) {
            float w = WS[30+dy*3+dx];
            c3v[0] = fmaf(w, t[2+dx], c3v[0]);
            c3v[1] = fmaf(w, t[3+dx], c3v[1]);
            c3v[2] = fmaf(w, t[4+dx], c3v[2]);
            c3v[3] = fmaf(w, t[5+dx], c3v[3]);
        }
    }

    float a1 = s1[c], a2 = s2[c], a3 = s3[c];
    float cst = fmaf(a1, b1[c], bb1[c]) + fmaf(a2, b2[c], bb2[c]) + fmaf(a3, b3[c], bb3[c]);
    float o0 = fmaf(a1, c1v[0], fmaf(a2, c2v[0], fmaf(a3, c3v[0], cst)));
    float o1 = fmaf(a1, c1v[1], fmaf(a2, c2v[1], fmaf(a3, c3v[1], cst)));
    float o2 = fmaf(a1, c1v[2], fmaf(a2, c2v[2], fmaf(a3, c3v[2], cst)));
    float o3 = fmaf(a1, c1v[3], fmaf(a2, c2v[3], fmaf(a3, c3v[3], cst)));

    __half2 h0 = __floats2half2_rn(o0, o1);
    __half2 h1 = __floats2half2_rn(o2, o3);
    uint2 pkd = make_uint2(*(unsigned*)&h0, *(unsigned*)&h1);
    *(uint2*)&g_s[(size_t)(b*Cv+c)*HWv + (gy0+ty)*Wv + p0] = pkd;
}

// ---------------------------------------------------------------------------
// Kernel 2: off = bn4(bias(1x1 conv C->18 of s)) — split-channel, 128 threads
// ---------------------------------------------------------------------------
__global__ __launch_bounds__(128)
void k_off(const float* __restrict__ balw, const float* __restrict__ balb,
           const float* __restrict__ s4,   const float* __restrict__ b4)
{
    __shared__ float BW[64*18];
    __shared__ float PACC[64*19];
    int tid = threadIdx.x;
    int b = blockIdx.y;
    int px = tid & 63, ch0 = (tid >> 6) * 32;
    int pix = blockIdx.x*64 + px;
    for (int t = tid; t < 64*18; t += 128) {
        int c = t/18, j = t%18;
        BW[t] = balw[j*64 + c];           // BW[c*18+j]
    }
    __syncthreads();

    float acc[18];
#pragma unroll
    for (int j = 0; j < 18; j++) acc[j] = 0.f;

    const __half* sp = g_s + (size_t)b*Cv*HWv + (size_t)ch0*HWv + pix;
#pragma unroll 8
    for (int c = 0; c < 32; c++) {
        float v = __half2float(sp[(size_t)c*HWv]);
        const float* bwc = &BW[(ch0+c)*18];
#pragma unroll
        for (int j = 0; j < 18; j++) acc[j] = fmaf(bwc[j], v, acc[j]);
    }

    if (tid >= 64) {
#pragma unroll
        for (int j = 0; j < 18; j++) PACC[px*19 + j] = acc[j];
    }
    __syncthreads();
    if (tid < 64) {
#pragma unroll
        for (int j = 0; j < 18; j++)
            g_off[((size_t)b*18 + j)*HWv + pix] =
                fmaf(s4[j], acc[j] + PACC[px*19 + j] + balb[j], b4[j]);
    }
}

// ---------------------------------------------------------------------------
// Kernel 3: sum of 4 deformable depthwise convs (d = 2,3,4,5), shared offsets.
// fp16 sample tile; bilinear in half2, fp32 accumulate; fp16 dsum store.
// ---------------------------------------------------------------------------
__device__ __forceinline__ void bil8h(uint4 a, uint4 b, uint4 c, uint4 d,
                                      __half2 h00, __half2 h01, __half2 h10, __half2 h11,
                                      float4 dq0, float4 dq1, float* acc)
{
    const __half2* pa = (const __half2*)&a;
    const __half2* pb = (const __half2*)&b;
    const __half2* pc = (const __half2*)&c;
    const __half2* pd = (const __half2*)&d;
    float dw[8] = {dq0.x,dq0.y,dq0.z,dq0.w,dq1.x,dq1.y,dq1.z,dq1.w};
#pragma unroll
    for (int j = 0; j < 4; j++) {
        __half2 v = __hmul2(h00, pa[j]);
        v = __hfma2(h01, pb[j], v);
        v = __hfma2(h10, pc[j], v);
        v = __hfma2(h11, pd[j], v);
        float2 vf = __half22float2(v);
        acc[2*j]   = fmaf(dw[2*j],   vf.x, acc[2*j]);
        acc[2*j+1] = fmaf(dw[2*j+1], vf.y, acc[2*j+1]);
    }
}

#define FASTSAMPLE(L, dwq) {                                   \
    uint4 u00 = *(const uint4*)&XS[(L)*8];                     \
    uint4 u01 = *(const uint4*)&XS[((L)+1)*8];                 \
    uint4 u10 = *(const uint4*)&XS[((L)+46)*8];                \
    uint4 u11 = *(const uint4*)&XS[((L)+47)*8];                \
    bil8h(u00,u01,u10,u11, h00,h01,h10,h11, (dwq)[0], (dwq)[1], acc); \
}

__global__ __launch_bounds__(256)
void k_deform(const float* __restrict__ x,
              const float* __restrict__ dw2, const float* __restrict__ dw3,
              const float* __restrict__ dw4, const float* __restrict__ dw5)
{
    __shared__ __half XS[1012*8];  // [loc = yy*46+xx][ci] — 16B per loc
    __shared__ float DWT[4*9*8];   // [di][k][ci]
    int tid = threadIdx.y*32 + threadIdx.x;
    int b  = blockIdx.z >> 3;
    int c0 = (blockIdx.z & 7) * 8;
    int gy0 = blockIdx.y*8, gx0 = blockIdx.x*32;
    const float* xb = x + (size_t)(b*Cv + c0)*HWv;

    for (int i = tid; i < 8096; i += 256) {
        int ci = i / 1012, loc = i % 1012;
        int yy = loc / 46, xx = loc % 46;
        int gy = gy0 - 7 + yy, gx = gx0 - 7 + xx;
        float v = (gy>=0 && gy<Hv && gx>=0 && gx<Wv) ? xb[(size_t)ci*HWv + gy*Wv + gx] : 0.f;
        XS[loc*8 + ci] = __float2half(v);
    }
    for (int t = tid; t < 288; t += 256) {
        int di = t/72, r = t%72, k = r/8, ci = r%8;
        const float* dp = (di==0)?dw2:(di==1)?dw3:(di==2)?dw4:dw5;
        DWT[t] = dp[(c0+ci)*9 + k];
    }
    __syncthreads();

    int gw = gx0 + threadIdx.x, gh = gy0 + threadIdx.y;
    int pix = gh*Wv + gw;

    float acc[8];
#pragma unroll
    for (int ci = 0; ci < 8; ci++) acc[ci] = 0.f;

    const float* op = g_off + (size_t)b*18*HWv + pix;

#pragma unroll
    for (int k = 0; k < 9; k++) {
        const int ky = k/3 - 1, kx = k%3 - 1;
        float py = op[(size_t)(2*k  )*HWv] + (float)gh;
        float px = op[(size_t)(2*k+1)*HWv] + (float)gw;
        float fy = floorf(py), fx = floorf(px);
        float wy = py - fy, wx = px - fx;
        int y0b = (int)fy, x0b = (int)fx;
        float w11 = wy*wx;
        float w10 = wy - w11;
        float w01 = wx - w11;
        float w00 = 1.f - wy - wx + w11;
        __half2 h00 = __float2half2_rn(w00);
        __half2 h01 = __float2half2_rn(w01);
        __half2 h10 = __float2half2_rn(w10);
        __half2 h11 = __float2half2_rn(w11);

        int rely = y0b - gy0 + 7, relx = x0b - gx0 + 7;
        const int kylo = (ky > 0) ? 2*ky : 5*ky;
        const int kyhi = (ky > 0) ? 5*ky : 2*ky;
        const int kxlo = (kx > 0) ? 2*kx : 5*kx;
        const int kxhi = (kx > 0) ? 5*kx : 2*kx;
        bool allfast = (rely + kylo >= 0) && (rely + kyhi <= 20) &&
                       (relx + kxlo >= 0) && (relx + kxhi <= 44);

        if (allfast) {
#pragma unroll
            for (int di = 0; di < 4; di++) {
                int d = di + 2;
                int L = (rely + d*ky)*46 + (relx + d*kx);
                const float4* dwq = (const float4*)&DWT[(di*9 + k)*8];
                FASTSAMPLE(L, dwq);
            }
        } else {
#pragma unroll
            for (int di = 0; di < 4; di++) {
                int d = di + 2;
                int y0 = y0b + d*ky, x0 = x0b + d*kx;
                int sy = y0 - gy0 + 7, sx = x0 - gx0 + 7;
                const float4* dwq = (const float4*)&DWT[(di*9 + k)*8];
                if (sy >= 0 && sy <= 20 && sx >= 0 && sx <= 44) {
                    int L = sy*46 + sx;
                    FASTSAMPLE(L, dwq);
                } else {
                    int y1 = y0 + 1, x1 = x0 + 1;
                    bool vy0 = (y0>=0)&&(y0<Hv), vy1 = (y1>=0)&&(y1<Hv);
                    bool vx0 = (x0>=0)&&(x0<Wv), vx1 = (x1>=0)&&(x1<Wv);
                    int iy0 = vy0? y0:0, iy1 = vy1? y1:0;
                    int ix0 = vx0? x0:0, ix1 = vx1? x1:0;
                    const float* dwf = (const float*)dwq;
#pragma unroll
                    for (int ci = 0; ci < 8; ci++) {
                        const float* xc = xb + (size_t)ci*HWv;
                        float g00 = (vy0&&vx0)? xc[iy0*Wv+ix0] : 0.f;
                        float g01 = (vy0&&vx1)? xc[iy0*Wv+ix1] : 0.f;
                        float g10 = (vy1&&vx0)? xc[iy1*Wv+ix0] : 0.f;
                        float g11 = (vy1&&vx1)? xc[iy1*Wv+ix1] : 0.f;
                        float v = w00*g00 + w01*g01 + w10*g10 + w11*g11;
                        acc[ci] = fmaf(dwf[ci], v, acc[ci]);
                    }
                }
            }
        }
    }
    __half* outp = g_dsum + (size_t)(b*Cv + c0)*HWv + pix;
#pragma unroll
    for (int ci = 0; ci < 8; ci++) outp[(size_t)ci*HWv] = __float2half(acc[ci]);
}

// ---------------------------------------------------------------------------
// Kernel 4: out = bn5(bias(fin_w @ dsum)) * x, tiled GEMM (R9/R12 shape).
// ---------------------------------------------------------------------------
__global__ __launch_bounds__(256)
void k_final(const float* __restrict__ x,
             const float* __restrict__ fw, const float* __restrict__ fb,
             const float* __restrict__ s5, const float* __restrict__ b5,
             float* __restrict__ out)
{
    __shared__ float FWs[64*34];   // FWs[cin*34+co] = fw[(cog*32+co)*64+cin]
    __shared__ float DS[64*64];    // DS[cin*64+p]
    int tid = threadIdx.x;
    int b   = blockIdx.z;
    int cog = blockIdx.y;          // cout half: couts cog*32 .. cog*32+31
    int pix0 = blockIdx.x*64;

    const float* fwh = fw + (size_t)cog*32*64;
    for (int i = tid; i < 2048; i += 256) {
        int co = i >> 6, cin = i & 63;
        FWs[cin*34 + co] = fwh[i];
    }
    const __half* dp = g_dsum + (size_t)b*Cv*HWv + pix0;
    for (int i = tid; i < 1024; i += 256) {
        int cin = i >> 4, p4 = i & 15;
        uint2 u = *(const uint2*)(dp + (size_t)cin*HWv + p4*4);   // 4 halves
        float2 f0 = __half22float2(*(const __half2*)&u.x);
        float2 f1 = __half22float2(*(const __half2*)&u.y);
        ((float4*)DS)[cin*16 + p4] = make_float4(f0.x, f0.y, f1.x, f1.y);
    }
    __syncthreads();

    int tp = tid & 15;        // pixels tp*4 .. tp*4+3
    int tc = tid >> 4;        // local couts tc*2, tc*2+1
    float4 a0 = {0,0,0,0}, a1 = {0,0,0,0};

#pragma unroll 8
    for (int cin = 0; cin < 64; cin++) {
        float4 d = *(const float4*)&DS[cin*64 + tp*4];
        float2 w = *(const float2*)&FWs[cin*34 + tc*2];
        a0.x = fmaf(w.x, d.x, a0.x); a0.y = fmaf(w.x, d.y, a0.y);
        a0.z = fmaf(w.x, d.z, a0.z); a0.w = fmaf(w.x, d.w, a0.w);
        a1.x = fmaf(w.y, d.x, a1.x); a1.y = fmaf(w.y, d.y, a1.y);
        a1.z = fmaf(w.y, d.z, a1.z); a1.w = fmaf(w.y, d.w, a1.w);
    }

    float4 accs[2] = {a0, a1};
#pragma unroll
    for (int i = 0; i < 2; i++) {
        int j = cog*32 + tc*2 + i;
        float sc = s5[j], fbj = fb[j], bbj = b5[j];
        size_t o = (size_t)(b*Cv + j)*HWv + pix0 + tp*4;
        float4 xv = *(const float4*)(x + o);
        float4 r;
        r.x = fmaf(sc, accs[i].x + fbj, bbj) * xv.x;
        r.y = fmaf(sc, accs[i].y + fbj, bbj) * xv.y;
        r.z = fmaf(sc, accs[i].z + fbj, bbj) * xv.z;
        r.w = fmaf(sc, accs[i].w + fbj, bbj) * xv.w;
        *(float4*)(out + o) = r;
    }
}

// ---------------------------------------------------------------------------
extern "C" void kernel_launch(void* const* d_in, const int* in_sizes, int n_in,
                              void* d_out, int out_size)
{
    int ix, i_off1w, i_off1b, i_bn1s, i_bn1b, i_off2w, i_off2b, i_bn2s, i_bn2b,
        i_off3w, i_off3b, i_bn3s, i_bn3b, i_balw, i_balb, i_bn4s, i_bn4b,
        i_dw2, i_dw3, i_dw4, i_dw5, i_finw, i_finb, i_bn5s, i_bn5b;

    if (in_sizes[0] == Bv*Cv*HWv) {
        ix=0;  i_off1w=1;  i_off1b=2;  i_bn1s=3;  i_bn1b=4;
        i_off2w=5;  i_off2b=6;  i_bn2s=7;  i_bn2b=8;
        i_off3w=9;  i_off3b=10; i_bn3s=11; i_bn3b=12;
        i_balw=13; i_balb=14; i_bn4s=15; i_bn4b=16;
        i_dw2=17; i_dw3=18; i_dw4=19; i_dw5=20;
        i_finw=21; i_finb=22; i_bn5s=23; i_bn5b=24;
    } else {
        i_balb=0; i_balw=1; i_bn1b=2; i_bn1s=3; i_bn2b=4; i_bn2s=5;
        i_bn3b=6; i_bn3s=7; i_bn4b=8; i_bn4s=9; i_bn5b=10; i_bn5s=11;
        i_dw2=12; i_dw3=13; i_dw4=14; i_dw5=15;
        i_finb=16; i_finw=17; i_off1b=18; i_off1w=19;
        i_off2b=20; i_off2w=21; i_off3b=22; i_off3w=23; ix=24;
    }

    const float* x      = (const float*)d_in[ix];
    const float* off1_w = (const float*)d_in[i_off1w];
    const float* off1_b = (const float*)d_in[i_off1b];
    const float* bn1_s  = (const float*)d_in[i_bn1s];
    const float* bn1_b  = (const float*)d_in[i_bn1b];
    const float* off2_w = (const float*)d_in[i_off2w];
    const float* off2_b = (const float*)d_in[i_off2b];
    const float* bn2_s  = (const float*)d_in[i_bn2s];
    const float* bn2_b  = (const float*)d_in[i_bn2b];
    const float* off3_w = (const float*)d_in[i_off3w];
    const float* off3_b = (const float*)d_in[i_off3b];
    const float* bn3_s  = (const float*)d_in[i_bn3s];
    const float* bn3_b  = (const float*)d_in[i_bn3b];
    const float* bal_w  = (const float*)d_in[i_balw];
    const float* bal_b  = (const float*)d_in[i_balb];
    const float* bn4_s  = (const float*)d_in[i_bn4s];
    const float* bn4_b  = (const float*)d_in[i_bn4b];
    const float* dw2    = (const float*)d_in[i_dw2];
    const float* dw3    = (const float*)d_in[i_dw3];
    const float* dw4    = (const float*)d_in[i_dw4];
    const float* dw5    = (const float*)d_in[i_dw5];
    const float* fin_w  = (const float*)d_in[i_finw];
    const float* fin_b  = (const float*)d_in[i_finb];
    const float* bn5_s  = (const float*)d_in[i_bn5s];
    const float* bn5_b  = (const float*)d_in[i_bn5b];
    float* out = (float*)d_out;

    dim3 blk(32, 8);
    k_branch<<<dim3(1, 16, Bv*Cv), blk>>>(x,
        off1_w, off1_b, bn1_s, bn1_b,
        off2_w, off2_b, bn2_s, bn2_b,
        off3_w, off3_b, bn3_s, bn3_b);
    k_off<<<dim3(HWv/64, Bv), 128>>>(bal_w, bal_b, bn4_s, bn4_b);
    k_deform<<<dim3(4, 16, Bv*8), blk>>>(x, dw2, dw3, dw4, dw5);
    k_final<<<dim3(HWv/64, 2, Bv), 256>>>(x, fin_w, fin_b, bn5_s, bn5_b, out);
}

// round 15
// speedup vs baseline: 2.0016x; 1.0469x over previous
#include <cuda_runtime.h>
#include <cuda_fp16.h>

#define Bv 2
#define Cv 64
#define Hv 128
#define Wv 128
#define HWv (Hv*Wv)

// Scratch buffers (static __device__ — no runtime allocation)
__device__ __half g_s[Bv*Cv*HWv];      // o1+o2+o3 fused branch output (fp16)
__device__ float  g_off[Bv*18*HWv];    // 18 offset channels
__device__ __half g_dsum[Bv*Cv*HWv];   // sum of 4 deformable convs (fp16)

// ---------------------------------------------------------------------------
// Kernel 1: s = bn1(bias(dw 1x15)) + bn2(bias(dw 15x1)) + bn3(bias(dw 3x3))
// Full-width tile (144-pad x 22 rows), thread computes 4 consecutive pixels.
// ---------------------------------------------------------------------------
__global__ __launch_bounds__(256)
void k_branch(const float* __restrict__ x,
              const float* __restrict__ w1, const float* __restrict__ b1,
              const float* __restrict__ s1, const float* __restrict__ bb1,
              const float* __restrict__ w2, const float* __restrict__ b2,
              const float* __restrict__ s2, const float* __restrict__ bb2,
              const float* __restrict__ w3, const float* __restrict__ b3,
              const float* __restrict__ s3, const float* __restrict__ bb3)
{
    __shared__ float XS[22*144];   // rows gy0-7..gy0+14, cols gx -7..136 (pad)
    __shared__ float WS[39];
    int tid = threadIdx.y*32 + threadIdx.x;
    int b = blockIdx.z / Cv, c = blockIdx.z % Cv;
    int gy0 = blockIdx.y*8;
    const float* xc = x + (size_t)(b*Cv + c)*HWv;

    for (int i = tid; i < 22*144; i += 256) {
        int yy = i / 144, xx = i - yy*144;
        int gy = gy0 - 7 + yy, gx = xx - 7;
        XS[i] = (gy>=0 && gy<Hv && gx>=0 && gx<Wv) ? xc[gy*Wv+gx] : 0.f;
    }
    if (tid < 15)       WS[tid] = w1[c*15 + tid];
    else if (tid < 30)  WS[tid] = w2[c*15 + tid-15];
    else if (tid < 39)  WS[tid] = w3[c*9  + tid-30];
    __syncthreads();

    int tx = threadIdx.x, ty = threadIdx.y;
    int p0 = tx*4;                 // pixel cols p0..p0+3

    float c1v[4] = {0,0,0,0};
    {
        const float* row = &XS[(ty+7)*144 + p0];
        float r[20];
#pragma unroll
        for (int q = 0; q < 5; q++) *(float4*)&r[q*4] = *(const float4*)&row[q*4];
#pragma unroll
        for (int i = 0; i < 15; i++) {
            float w = WS[i];
            c1v[0] = fmaf(w, r[i],   c1v[0]);
            c1v[1] = fmaf(w, r[i+1], c1v[1]);
            c1v[2] = fmaf(w, r[i+2], c1v[2]);
            c1v[3] = fmaf(w, r[i+3], c1v[3]);
        }
    }

    float c2v[4] = {0,0,0,0};
#pragma unroll
    for (int i = 0; i < 15; i++) {
        const float* rw = &XS[(ty+i)*144 + p0 + 4];
        float4 a  = *(const float4*)rw;
        float4 bq = *(const float4*)(rw + 4);
        float w = WS[15+i];
        c2v[0] = fmaf(w, a.w,  c2v[0]);
        c2v[1] = fmaf(w, bq.x, c2v[1]);
        c2v[2] = fmaf(w, bq.y, c2v[2]);
        c2v[3] = fmaf(w, bq.z, c2v[3]);
    }

    float c3v[4] = {0,0,0,0};
#pragma unroll
    for (int dy = 0; dy < 3; dy++) {
        const float* rw = &XS[(ty+6+dy)*144 + p0 + 4];
        float t[8];
        *(float4*)&t[0] = *(const float4*)rw;
        *(float4*)&t[4] = *(const float4*)(rw + 4);
#pragma unroll
        for (int dx = 0; dx < 3; dx++) {
            float w = WS[30+dy*3+dx];
            c3v[0] = fmaf(w, t[2+dx], c3v[0]);
            c3v[1] = fmaf(w, t[3+dx], c3v[1]);
            c3v[2] = fmaf(w, t[4+dx], c3v[2]);
            c3v[3] = fmaf(w, t[5+dx], c3v[3]);
        }
    }

    float a1 = s1[c], a2 = s2[c], a3 = s3[c];
    float cst = fmaf(a1, b1[c], bb1[c]) + fmaf(a2, b2[c], bb2[c]) + fmaf(a3, b3[c], bb3[c]);
    float o0 = fmaf(a1, c1v[0], fmaf(a2, c2v[0], fmaf(a3, c3v[0], cst)));
    float o1 = fmaf(a1, c1v[1], fmaf(a2, c2v[1], fmaf(a3, c3v[1], cst)));
    float o2 = fmaf(a1, c1v[2], fmaf(a2, c2v[2], fmaf(a3, c3v[2], cst)));
    float o3 = fmaf(a1, c1v[3], fmaf(a2, c2v[3], fmaf(a3, c3v[3], cst)));

    __half2 h0 = __floats2half2_rn(o0, o1);
    __half2 h1 = __floats2half2_rn(o2, o3);
    uint2 pkd = make_uint2(*(unsigned*)&h0, *(unsigned*)&h1);
    *(uint2*)&g_s[(size_t)(b*Cv+c)*HWv + (gy0+ty)*Wv + p0] = pkd;
}

// ---------------------------------------------------------------------------
// Kernel 2: off = bn4(bias(1x1 conv C->18 of s)) — split-channel, 128 threads
// ---------------------------------------------------------------------------
__global__ __launch_bounds__(128)
void k_off(const float* __restrict__ balw, const float* __restrict__ balb,
           const float* __restrict__ s4,   const float* __restrict__ b4)
{
    __shared__ float BW[64*18];
    __shared__ float PACC[64*19];
    int tid = threadIdx.x;
    int b = blockIdx.y;
    int px = tid & 63, ch0 = (tid >> 6) * 32;
    int pix = blockIdx.x*64 + px;
    for (int t = tid; t < 64*18; t += 128) {
        int c = t/18, j = t%18;
        BW[t] = balw[j*64 + c];           // BW[c*18+j]
    }
    __syncthreads();

    float acc[18];
#pragma unroll
    for (int j = 0; j < 18; j++) acc[j] = 0.f;

    const __half* sp = g_s + (size_t)b*Cv*HWv + (size_t)ch0*HWv + pix;
#pragma unroll 8
    for (int c = 0; c < 32; c++) {
        float v = __half2float(sp[(size_t)c*HWv]);
        const float* bwc = &BW[(ch0+c)*18];
#pragma unroll
        for (int j = 0; j < 18; j++) acc[j] = fmaf(bwc[j], v, acc[j]);
    }

    if (tid >= 64) {
#pragma unroll
        for (int j = 0; j < 18; j++) PACC[px*19 + j] = acc[j];
    }
    __syncthreads();
    if (tid < 64) {
#pragma unroll
        for (int j = 0; j < 18; j++)
            g_off[((size_t)b*18 + j)*HWv + pix] =
                fmaf(s4[j], acc[j] + PACC[px*19 + j] + balb[j], b4[j]);
    }
}

// ---------------------------------------------------------------------------
// Kernel 3: sum of 4 deformable depthwise convs (d = 2,3,4,5), shared offsets.
// fp16 sample tile; bilinear in half2, fp32 accumulate; fp16 dsum store.
// R14: offsets preloaded into registers (kills per-k serialized LDG chains),
// warp-uniform fast-path vote (no divergence bookkeeping on the common path).
// ---------------------------------------------------------------------------
__device__ __forceinline__ void bil8h(uint4 a, uint4 b, uint4 c, uint4 d,
                                      __half2 h00, __half2 h01, __half2 h10, __half2 h11,
                                      float4 dq0, float4 dq1, float* acc)
{
    const __half2* pa = (const __half2*)&a;
    const __half2* pb = (const __half2*)&b;
    const __half2* pc = (const __half2*)&c;
    const __half2* pd = (const __half2*)&d;
    float dw[8] = {dq0.x,dq0.y,dq0.z,dq0.w,dq1.x,dq1.y,dq1.z,dq1.w};
#pragma unroll
    for (int j = 0; j < 4; j++) {
        __half2 v = __hmul2(h00, pa[j]);
        v = __hfma2(h01, pb[j], v);
        v = __hfma2(h10, pc[j], v);
        v = __hfma2(h11, pd[j], v);
        float2 vf = __half22float2(v);
        acc[2*j]   = fmaf(dw[2*j],   vf.x, acc[2*j]);
        acc[2*j+1] = fmaf(dw[2*j+1], vf.y, acc[2*j+1]);
    }
}

#define FASTSAMPLE(L, dwq) {                                   \
    uint4 u00 = *(const uint4*)&XS[(L)*8];                     \
    uint4 u01 = *(const uint4*)&XS[((L)+1)*8];                 \
    uint4 u10 = *(const uint4*)&XS[((L)+46)*8];                \
    uint4 u11 = *(const uint4*)&XS[((L)+47)*8];                \
    bil8h(u00,u01,u10,u11, h00,h01,h10,h11, (dwq)[0], (dwq)[1], acc); \
}

__global__ __launch_bounds__(256)
void k_deform(const float* __restrict__ x,
              const float* __restrict__ dw2, const float* __restrict__ dw3,
              const float* __restrict__ dw4, const float* __restrict__ dw5)
{
    __shared__ __half XS[1012*8];  // [loc = yy*46+xx][ci] — 16B per loc
    __shared__ float DWT[4*9*8];   // [di][k][ci]
    int tid = threadIdx.y*32 + threadIdx.x;
    int b  = blockIdx.z >> 3;
    int c0 = (blockIdx.z & 7) * 8;
    int gy0 = blockIdx.y*8, gx0 = blockIdx.x*32;
    const float* xb = x + (size_t)(b*Cv + c0)*HWv;

    for (int i = tid; i < 8096; i += 256) {
        int ci = i / 1012, loc = i % 1012;
        int yy = loc / 46, xx = loc % 46;
        int gy = gy0 - 7 + yy, gx = gx0 - 7 + xx;
        float v = (gy>=0 && gy<Hv && gx>=0 && gx<Wv) ? xb[(size_t)ci*HWv + gy*Wv + gx] : 0.f;
        XS[loc*8 + ci] = __float2half(v);
    }
    for (int t = tid; t < 288; t += 256) {
        int di = t/72, r = t%72, k = r/8, ci = r%8;
        const float* dp = (di==0)?dw2:(di==1)?dw3:(di==2)?dw4:dw5;
        DWT[t] = dp[(c0+ci)*9 + k];
    }
    __syncthreads();

    int gw = gx0 + threadIdx.x, gh = gy0 + threadIdx.y;
    int pix = gh*Wv + gw;

    // Preload all 18 offsets up front — back-to-back LDGs, MLP ~18
    float offy[9], offx[9];
    const float* op = g_off + (size_t)b*18*HWv + pix;
#pragma unroll
    for (int k = 0; k < 9; k++) {
        offy[k] = op[(size_t)(2*k  )*HWv];
        offx[k] = op[(size_t)(2*k+1)*HWv];
    }

    float acc[8];
#pragma unroll
    for (int ci = 0; ci < 8; ci++) acc[ci] = 0.f;

#pragma unroll
    for (int k = 0; k < 9; k++) {
        const int ky = k/3 - 1, kx = k%3 - 1;
        float py = offy[k] + (float)gh;
        float px = offx[k] + (float)gw;
        float fy = floorf(py), fx = floorf(px);
        float wy = py - fy, wx = px - fx;
        int y0b = (int)fy, x0b = (int)fx;
        float w11 = wy*wx;
        float w10 = wy - w11;
        float w01 = wx - w11;
        float w00 = 1.f - wy - wx + w11;
        __half2 h00 = __float2half2_rn(w00);
        __half2 h01 = __float2half2_rn(w01);
        __half2 h10 = __float2half2_rn(w10);
        __half2 h11 = __float2half2_rn(w11);

        int rely = y0b - gy0 + 7, relx = x0b - gx0 + 7;
        const int kylo = (ky > 0) ? 2*ky : 5*ky;
        const int kyhi = (ky > 0) ? 5*ky : 2*ky;
        const int kxlo = (kx > 0) ? 2*kx : 5*kx;
        const int kxhi = (kx > 0) ? 5*kx : 2*kx;
        bool allfast = (rely + kylo >= 0) && (rely + kyhi <= 20) &&
                       (relx + kxlo >= 0) && (relx + kxhi <= 44);

        if (__all_sync(0xffffffffu, allfast)) {
            // whole warp on fast path — uniform branch, no divergence
#pragma unroll
            for (int di = 0; di < 4; di++) {
                int d = di + 2;
                int L = (rely + d*ky)*46 + (relx + d*kx);
                const float4* dwq = (const float4*)&DWT[(di*9 + k)*8];
                FASTSAMPLE(L, dwq);
            }
        } else {
#pragma unroll
            for (int di = 0; di < 4; di++) {
                int d = di + 2;
                int y0 = y0b + d*ky, x0 = x0b + d*kx;
                int sy = y0 - gy0 + 7, sx = x0 - gx0 + 7;
                const float4* dwq = (const float4*)&DWT[(di*9 + k)*8];
                if (sy >= 0 && sy <= 20 && sx >= 0 && sx <= 44) {
                    int L = sy*46 + sx;
                    FASTSAMPLE(L, dwq);
                } else {
                    int y1 = y0 + 1, x1 = x0 + 1;
                    bool vy0 = (y0>=0)&&(y0<Hv), vy1 = (y1>=0)&&(y1<Hv);
                    bool vx0 = (x0>=0)&&(x0<Wv), vx1 = (x1>=0)&&(x1<Wv);
                    int iy0 = vy0? y0:0, iy1 = vy1? y1:0;
                    int ix0 = vx0? x0:0, ix1 = vx1? x1:0;
                    const float* dwf = (const float*)dwq;
#pragma unroll
                    for (int ci = 0; ci < 8; ci++) {
                        const float* xc = xb + (size_t)ci*HWv;
                        float g00 = (vy0&&vx0)? xc[iy0*Wv+ix0] : 0.f;
                        float g01 = (vy0&&vx1)? xc[iy0*Wv+ix1] : 0.f;
                        float g10 = (vy1&&vx0)? xc[iy1*Wv+ix0] : 0.f;
                        float g11 = (vy1&&vx1)? xc[iy1*Wv+ix1] : 0.f;
                        float v = w00*g00 + w01*g01 + w10*g10 + w11*g11;
                        acc[ci] = fmaf(dwf[ci], v, acc[ci]);
                    }
                }
            }
        }
    }
    __half* outp = g_dsum + (size_t)(b*Cv + c0)*HWv + pix;
#pragma unroll
    for (int ci = 0; ci < 8; ci++) outp[(size_t)ci*HWv] = __float2half(acc[ci]);
}

// ---------------------------------------------------------------------------
// Kernel 4: out = bn5(bias(fin_w @ dsum)) * x, tiled GEMM (R9/R12 shape).
// R14: DS kept as fp16 in SMEM — d-read per cin drops 16B -> 8B/thread
// (crossbar halves on the pixel-operand side); fp32 accumulate unchanged.
// ---------------------------------------------------------------------------
__global__ __launch_bounds__(256)
void k_final(const float* __restrict__ x,
             const float* __restrict__ fw, const float* __restrict__ fb,
             const float* __restrict__ s5, const float* __restrict__ b5,
             float* __restrict__ out)
{
    __shared__ float  FWs[64*34];   // FWs[cin*34+co] = fw[(cog*32+co)*64+cin]
    __shared__ __half DS[64*64];    // DS[cin*64+p] (fp16)
    int tid = threadIdx.x;
    int b   = blockIdx.z;
    int cog = blockIdx.y;          // cout half: couts cog*32 .. cog*32+31
    int pix0 = blockIdx.x*64;

    const float* fwh = fw + (size_t)cog*32*64;
    for (int i = tid; i < 2048; i += 256) {
        int co = i >> 6, cin = i & 63;
        FWs[cin*34 + co] = fwh[i];
    }
    const __half* dp = g_dsum + (size_t)b*Cv*HWv + pix0;
    for (int i = tid; i < 512; i += 256) {
        int cin = i >> 3, p8 = i & 7;
        ((uint4*)DS)[cin*8 + p8] = *(const uint4*)(dp + (size_t)cin*HWv + p8*8);
    }
    __syncthreads();

    int tp = tid & 15;        // pixels tp*4 .. tp*4+3
    int tc = tid >> 4;        // local couts tc*2, tc*2+1
    float4 a0 = {0,0,0,0}, a1 = {0,0,0,0};

#pragma unroll 8
    for (int cin = 0; cin < 64; cin++) {
        uint2 u = *(const uint2*)&DS[cin*64 + tp*4];
        float2 dlo = __half22float2(*(const __half2*)&u.x);
        float2 dhi = __half22float2(*(const __half2*)&u.y);
        float2 w = *(const float2*)&FWs[cin*34 + tc*2];
        a0.x = fmaf(w.x, dlo.x, a0.x); a0.y = fmaf(w.x, dlo.y, a0.y);
        a0.z = fmaf(w.x, dhi.x, a0.z); a0.w = fmaf(w.x, dhi.y, a0.w);
        a1.x = fmaf(w.y, dlo.x, a1.x); a1.y = fmaf(w.y, dlo.y, a1.y);
        a1.z = fmaf(w.y, dhi.x, a1.z); a1.w = fmaf(w.y, dhi.y, a1.w);
    }

    float4 accs[2] = {a0, a1};
#pragma unroll
    for (int i = 0; i < 2; i++) {
        int j = cog*32 + tc*2 + i;
        float sc = s5[j], fbj = fb[j], bbj = b5[j];
        size_t o = (size_t)(b*Cv + j)*HWv + pix0 + tp*4;
        float4 xv = *(const float4*)(x + o);
        float4 r;
        r.x = fmaf(sc, accs[i].x + fbj, bbj) * xv.x;
        r.y = fmaf(sc, accs[i].y + fbj, bbj) * xv.y;
        r.z = fmaf(sc, accs[i].z + fbj, bbj) * xv.z;
        r.w = fmaf(sc, accs[i].w + fbj, bbj) * xv.w;
        *(float4*)(out + o) = r;
    }
}

// ---------------------------------------------------------------------------
extern "C" void kernel_launch(void* const* d_in, const int* in_sizes, int n_in,
                              void* d_out, int out_size)
{
    int ix, i_off1w, i_off1b, i_bn1s, i_bn1b, i_off2w, i_off2b, i_bn2s, i_bn2b,
        i_off3w, i_off3b, i_bn3s, i_bn3b, i_balw, i_balb, i_bn4s, i_bn4b,
        i_dw2, i_dw3, i_dw4, i_dw5, i_finw, i_finb, i_bn5s, i_bn5b;

    if (in_sizes[0] == Bv*Cv*HWv) {
        ix=0;  i_off1w=1;  i_off1b=2;  i_bn1s=3;  i_bn1b=4;
        i_off2w=5;  i_off2b=6;  i_bn2s=7;  i_bn2b=8;
        i_off3w=9;  i_off3b=10; i_bn3s=11; i_bn3b=12;
        i_balw=13; i_balb=14; i_bn4s=15; i_bn4b=16;
        i_dw2=17; i_dw3=18; i_dw4=19; i_dw5=20;
        i_finw=21; i_finb=22; i_bn5s=23; i_bn5b=24;
    } else {
        i_balb=0; i_balw=1; i_bn1b=2; i_bn1s=3; i_bn2b=4; i_bn2s=5;
        i_bn3b=6; i_bn3s=7; i_bn4b=8; i_bn4s=9; i_bn5b=10; i_bn5s=11;
        i_dw2=12; i_dw3=13; i_dw4=14; i_dw5=15;
        i_finb=16; i_finw=17; i_off1b=18; i_off1w=19;
        i_off2b=20; i_off2w=21; i_off3b=22; i_off3w=23; ix=24;
    }

    const float* x      = (const float*)d_in[ix];
    const float* off1_w = (const float*)d_in[i_off1w];
    const float* off1_b = (const float*)d_in[i_off1b];
    const float* bn1_s  = (const float*)d_in[i_bn1s];
    const float* bn1_b  = (const float*)d_in[i_bn1b];
    const float* off2_w = (const float*)d_in[i_off2w];
    const float* off2_b = (const float*)d_in[i_off2b];
    const float* bn2_s  = (const float*)d_in[i_bn2s];
    const float* bn2_b  = (const float*)d_in[i_bn2b];
    const float* off3_w = (const float*)d_in[i_off3w];
    const float* off3_b = (const float*)d_in[i_off3b];
    const float* bn3_s  = (const float*)d_in[i_bn3s];
    const float* bn3_b  = (const float*)d_in[i_bn3b];
    const float* bal_w  = (const float*)d_in[i_balw];
    const float* bal_b  = (const float*)d_in[i_balb];
    const float* bn4_s  = (const float*)d_in[i_bn4s];
    const float* bn4_b  = (const float*)d_in[i_bn4b];
    const float* dw2    = (const float*)d_in[i_dw2];
    const float* dw3    = (const float*)d_in[i_dw3];
    const float* dw4    = (const float*)d_in[i_dw4];
    const float* dw5    = (const float*)d_in[i_dw5];
    const float* fin_w  = (const float*)d_in[i_finw];
    const float* fin_b  = (const float*)d_in[i_finb];
    const float* bn5_s  = (const float*)d_in[i_bn5s];
    const float* bn5_b  = (const float*)d_in[i_bn5b];
    float* out = (float*)d_out;

    dim3 blk(32, 8);
    k_branch<<<dim3(1, 16, Bv*Cv), blk>>>(x,
        off1_w, off1_b, bn1_s, bn1_b,
        off2_w, off2_b, bn2_s, bn2_b,
        off3_w, off3_b, bn3_s, bn3_b);
    k_off<<<dim3(HWv/64, Bv), 128>>>(bal_w, bal_b, bn4_s, bn4_b);
    k_deform<<<dim3(4, 16, Bv*8), blk>>>(x, dw2, dw3, dw4, dw5);
    k_final<<<dim3(HWv/64, 2, Bv), 256>>>(x, fin_w, fin_b, bn5_s, bn5_b, out);
}

// round 17
// speedup vs baseline: 2.2328x; 1.1155x over previous
#include <cuda_runtime.h>
#include <cuda_fp16.h>

#define Bv 2
#define Cv 64
#define Hv 128
#define Wv 128
#define HWv (Hv*Wv)

// Scratch buffers (static __device__ — no runtime allocation)
__device__ __half g_s[Bv*Cv*HWv];      // o1+o2+o3 fused branch output (fp16)
__device__ float  g_off[Bv*18*HWv];    // 18 offset channels
__device__ __half g_dsum[Bv*Cv*HWv];   // sum of 4 deformable convs (fp16)

// ---------------------------------------------------------------------------
// Kernel 1: s = bn1(bias(dw 1x15)) + bn2(bias(dw 15x1)) + bn3(bias(dw 3x3))
// Halo-8 tile origin (gx = xx-8) makes c2's 4-px tap window quad-ALIGNED:
// per channel per thread: c1=5, c2=15, c3=6 LDS.128 (was 41).
// ---------------------------------------------------------------------------
__global__ __launch_bounds__(256)
void k_branch(const float* __restrict__ x,
              const float* __restrict__ w1, const float* __restrict__ b1,
              const float* __restrict__ s1, const float* __restrict__ bb1,
              const float* __restrict__ w2, const float* __restrict__ b2,
              const float* __restrict__ s2, const float* __restrict__ bb2,
              const float* __restrict__ w3, const float* __restrict__ b3,
              const float* __restrict__ s3, const float* __restrict__ bb3)
{
    __shared__ float XS[22*144];   // rows gy0-7..gy0+14, cols gx = xx-8 (-8..135)
    __shared__ float WS[39];
    int tid = threadIdx.y*32 + threadIdx.x;
    int b = blockIdx.z / Cv, c = blockIdx.z % Cv;
    int gy0 = blockIdx.y*8;
    const float* xc = x + (size_t)(b*Cv + c)*HWv;

    for (int i = tid; i < 22*144; i += 256) {
        int yy = i / 144, xx = i - yy*144;
        int gy = gy0 - 7 + yy, gx = xx - 8;
        XS[i] = (gy>=0 && gy<Hv && gx>=0 && gx<Wv) ? xc[gy*Wv+gx] : 0.f;
    }
    if (tid < 15)       WS[tid] = w1[c*15 + tid];
    else if (tid < 30)  WS[tid] = w2[c*15 + tid-15];
    else if (tid < 39)  WS[tid] = w3[c*9  + tid-30];
    __syncthreads();

    int tx = threadIdx.x, ty = threadIdx.y;
    int p0 = tx*4;                 // pixel cols p0..p0+3

    // c1: 1x15 row conv; taps xx = p0+1+i+j -> register window r[0..19]
    float c1v[4] = {0,0,0,0};
    {
        const float* row = &XS[(ty+7)*144 + p0];
        float r[20];
#pragma unroll
        for (int q = 0; q < 5; q++) *(float4*)&r[q*4] = *(const float4*)&row[q*4];
#pragma unroll
        for (int i = 0; i < 15; i++) {
            float w = WS[i];
            c1v[0] = fmaf(w, r[i+1], c1v[0]);
            c1v[1] = fmaf(w, r[i+2], c1v[1]);
            c1v[2] = fmaf(w, r[i+3], c1v[2]);
            c1v[3] = fmaf(w, r[i+4], c1v[3]);
        }
    }

    // c2: 15x1 col conv; taps xx = p0+8+j -> ONE aligned float4 per row.
    // c3: 3x3 on rows i=6..8; taps xx = p0+7+j+dx -> reuse c2 quad + 2 extra.
    float c2v[4] = {0,0,0,0};
    float c3v[4] = {0,0,0,0};
#pragma unroll
    for (int i = 0; i < 15; i++) {
        const float* rw = &XS[(ty+i)*144 + p0];
        float4 q2 = *(const float4*)(rw + 8);      // xx p0+8..p0+11
        float w = WS[15+i];
        c2v[0] = fmaf(w, q2.x, c2v[0]);
        c2v[1] = fmaf(w, q2.y, c2v[1]);
        c2v[2] = fmaf(w, q2.z, c2v[2]);
        c2v[3] = fmaf(w, q2.w, c2v[3]);
        if (i >= 6 && i <= 8) {
            int dy = i - 6;
            float4 q1 = *(const float4*)(rw + 4);  // xx p0+4..p0+7
            float4 q3 = *(const float4*)(rw + 12); // xx p0+12..p0+15
            float t[6] = {q1.w, q2.x, q2.y, q2.z, q2.w, q3.x}; // xx p0+7..p0+12
#pragma unroll
            for (int dx = 0; dx < 3; dx++) {
                float w3v = WS[30+dy*3+dx];
                c3v[0] = fmaf(w3v, t[0+dx], c3v[0]);
                c3v[1] = fmaf(w3v, t[1+dx], c3v[1]);
                c3v[2] = fmaf(w3v, t[2+dx], c3v[2]);
                c3v[3] = fmaf(w3v, t[3+dx], c3v[3]);
            }
        }
    }

    float a1 = s1[c], a2 = s2[c], a3 = s3[c];
    float cst = fmaf(a1, b1[c], bb1[c]) + fmaf(a2, b2[c], bb2[c]) + fmaf(a3, b3[c], bb3[c]);
    float o0 = fmaf(a1, c1v[0], fmaf(a2, c2v[0], fmaf(a3, c3v[0], cst)));
    float o1 = fmaf(a1, c1v[1], fmaf(a2, c2v[1], fmaf(a3, c3v[1], cst)));
    float o2 = fmaf(a1, c1v[2], fmaf(a2, c2v[2], fmaf(a3, c3v[2], cst)));
    float o3 = fmaf(a1, c1v[3], fmaf(a2, c2v[3], fmaf(a3, c3v[3], cst)));

    __half2 h0 = __floats2half2_rn(o0, o1);
    __half2 h1 = __floats2half2_rn(o2, o3);
    uint2 pkd = make_uint2(*(unsigned*)&h0, *(unsigned*)&h1);
    *(uint2*)&g_s[(size_t)(b*Cv+c)*HWv + (gy0+ty)*Wv + p0] = pkd;
}

// ---------------------------------------------------------------------------
// Kernel 2: off = bn4(bias(1x1 conv C->18 of s)) — split-channel, 128 threads
// ---------------------------------------------------------------------------
__global__ __launch_bounds__(128)
void k_off(const float* __restrict__ balw, const float* __restrict__ balb,
           const float* __restrict__ s4,   const float* __restrict__ b4)
{
    __shared__ float BW[64*18];
    __shared__ float PACC[64*19];
    int tid = threadIdx.x;
    int b = blockIdx.y;
    int px = tid & 63, ch0 = (tid >> 6) * 32;
    int pix = blockIdx.x*64 + px;
    for (int t = tid; t < 64*18; t += 128) {
        int c = t/18, j = t%18;
        BW[t] = balw[j*64 + c];           // BW[c*18+j]
    }
    __syncthreads();

    float acc[18];
#pragma unroll
    for (int j = 0; j < 18; j++) acc[j] = 0.f;

    const __half* sp = g_s + (size_t)b*Cv*HWv + (size_t)ch0*HWv + pix;
#pragma unroll 8
    for (int c = 0; c < 32; c++) {
        float v = __half2float(sp[(size_t)c*HWv]);
        const float* bwc = &BW[(ch0+c)*18];
#pragma unroll
        for (int j = 0; j < 18; j++) acc[j] = fmaf(bwc[j], v, acc[j]);
    }

    if (tid >= 64) {
#pragma unroll
        for (int j = 0; j < 18; j++) PACC[px*19 + j] = acc[j];
    }
    __syncthreads();
    if (tid < 64) {
#pragma unroll
        for (int j = 0; j < 18; j++)
            g_off[((size_t)b*18 + j)*HWv + pix] =
                fmaf(s4[j], acc[j] + PACC[px*19 + j] + balb[j], b4[j]);
    }
}

// ---------------------------------------------------------------------------
// Kernel 3: sum of 4 deformable depthwise convs (d = 2,3,4,5), shared offsets.
// fp16 sample tile; bilinear in half2, fp32 accumulate; fp16 dsum store.
// R16: dense per-loc fill — thread gathers 8 channels of one loc and writes
// a single STS.128 (was 2B scatter with 4-way conflicts).
// ---------------------------------------------------------------------------
__device__ __forceinline__ void bil8h(uint4 a, uint4 b, uint4 c, uint4 d,
                                      __half2 h00, __half2 h01, __half2 h10, __half2 h11,
                                      float4 dq0, float4 dq1, float* acc)
{
    const __half2* pa = (const __half2*)&a;
    const __half2* pb = (const __half2*)&b;
    const __half2* pc = (const __half2*)&c;
    const __half2* pd = (const __half2*)&d;
    float dw[8] = {dq0.x,dq0.y,dq0.z,dq0.w,dq1.x,dq1.y,dq1.z,dq1.w};
#pragma unroll
    for (int j = 0; j < 4; j++) {
        __half2 v = __hmul2(h00, pa[j]);
        v = __hfma2(h01, pb[j], v);
        v = __hfma2(h10, pc[j], v);
        v = __hfma2(h11, pd[j], v);
        float2 vf = __half22float2(v);
        acc[2*j]   = fmaf(dw[2*j],   vf.x, acc[2*j]);
        acc[2*j+1] = fmaf(dw[2*j+1], vf.y, acc[2*j+1]);
    }
}

#define FASTSAMPLE(L, dwq) {                                   \
    uint4 u00 = *(const uint4*)&XS[(L)*8];                     \
    uint4 u01 = *(const uint4*)&XS[((L)+1)*8];                 \
    uint4 u10 = *(const uint4*)&XS[((L)+46)*8];                \
    uint4 u11 = *(const uint4*)&XS[((L)+47)*8];                \
    bil8h(u00,u01,u10,u11, h00,h01,h10,h11, (dwq)[0], (dwq)[1], acc); \
}

__global__ __launch_bounds__(256)
void k_deform(const float* __restrict__ x,
              const float* __restrict__ dw2, const float* __restrict__ dw3,
              const float* __restrict__ dw4, const float* __restrict__ dw5)
{
    __shared__ __half XS[1012*8];  // [loc = yy*46+xx][ci] — 16B per loc
    __shared__ float DWT[4*9*8];   // [di][k][ci]
    int tid = threadIdx.y*32 + threadIdx.x;
    int b  = blockIdx.z >> 3;
    int c0 = (blockIdx.z & 7) * 8;
    int gy0 = blockIdx.y*8, gx0 = blockIdx.x*32;
    const float* xb = x + (size_t)(b*Cv + c0)*HWv;

    // Dense fill: one loc per thread-iteration, 8 coalesced LDG -> 1 STS.128
    for (int loc = tid; loc < 1012; loc += 256) {
        int yy = loc / 46, xx = loc - yy*46;
        int gy = gy0 - 7 + yy, gx = gx0 - 7 + xx;
        float v[8];
        if (gy>=0 && gy<Hv && gx>=0 && gx<Wv) {
            const float* p = xb + gy*Wv + gx;
#pragma unroll
            for (int ci = 0; ci < 8; ci++) v[ci] = p[(size_t)ci*HWv];
        } else {
#pragma unroll
            for (int ci = 0; ci < 8; ci++) v[ci] = 0.f;
        }
        __half2 h01v = __floats2half2_rn(v[0], v[1]);
        __half2 h23v = __floats2half2_rn(v[2], v[3]);
        __half2 h45v = __floats2half2_rn(v[4], v[5]);
        __half2 h67v = __floats2half2_rn(v[6], v[7]);
        uint4 pk;
        pk.x = *(unsigned*)&h01v; pk.y = *(unsigned*)&h23v;
        pk.z = *(unsigned*)&h45v; pk.w = *(unsigned*)&h67v;
        *(uint4*)&XS[loc*8] = pk;
    }
    for (int t = tid; t < 288; t += 256) {
        int di = t/72, r = t%72, k = r/8, ci = r%8;
        const float* dp = (di==0)?dw2:(di==1)?dw3:(di==2)?dw4:dw5;
        DWT[t] = dp[(c0+ci)*9 + k];
    }
    __syncthreads();

    int gw = gx0 + threadIdx.x, gh = gy0 + threadIdx.y;
    int pix = gh*Wv + gw;

    // Preload all 18 offsets up front — back-to-back LDGs, MLP ~18
    float offy[9], offx[9];
    const float* op = g_off + (size_t)b*18*HWv + pix;
#pragma unroll
    for (int k = 0; k < 9; k++) {
        offy[k] = op[(size_t)(2*k  )*HWv];
        offx[k] = op[(size_t)(2*k+1)*HWv];
    }

    float acc[8];
#pragma unroll
    for (int ci = 0; ci < 8; ci++) acc[ci] = 0.f;

#pragma unroll
    for (int k = 0; k < 9; k++) {
        const int ky = k/3 - 1, kx = k%3 - 1;
        float py = offy[k] + (float)gh;
        float px = offx[k] + (float)gw;
        float fy = floorf(py), fx = floorf(px);
        float wy = py - fy, wx = px - fx;
        int y0b = (int)fy, x0b = (int)fx;
        float w11 = wy*wx;
        float w10 = wy - w11;
        float w01 = wx - w11;
        float w00 = 1.f - wy - wx + w11;
        __half2 h00 = __float2half2_rn(w00);
        __half2 h01 = __float2half2_rn(w01);
        __half2 h10 = __float2half2_rn(w10);
        __half2 h11 = __float2half2_rn(w11);

        int rely = y0b - gy0 + 7, relx = x0b - gx0 + 7;
        const int kylo = (ky > 0) ? 2*ky : 5*ky;
        const int kyhi = (ky > 0) ? 5*ky : 2*ky;
        const int kxlo = (kx > 0) ? 2*kx : 5*kx;
        const int kxhi = (kx > 0) ? 5*kx : 2*kx;
        bool allfast = (rely + kylo >= 0) && (rely + kyhi <= 20) &&
                       (relx + kxlo >= 0) && (relx + kxhi <= 44);

        if (__all_sync(0xffffffffu, allfast)) {
#pragma unroll
            for (int di = 0; di < 4; di++) {
                int d = di + 2;
                int L = (rely + d*ky)*46 + (relx + d*kx);
                const float4* dwq = (const float4*)&DWT[(di*9 + k)*8];
                FASTSAMPLE(L, dwq);
            }
        } else {
#pragma unroll
            for (int di = 0; di < 4; di++) {
                int d = di + 2;
                int y0 = y0b + d*ky, x0 = x0b + d*kx;
                int sy = y0 - gy0 + 7, sx = x0 - gx0 + 7;
                const float4* dwq = (const float4*)&DWT[(di*9 + k)*8];
                if (sy >= 0 && sy <= 20 && sx >= 0 && sx <= 44) {
                    int L = sy*46 + sx;
                    FASTSAMPLE(L, dwq);
                } else {
                    int y1 = y0 + 1, x1 = x0 + 1;
                    bool vy0 = (y0>=0)&&(y0<Hv), vy1 = (y1>=0)&&(y1<Hv);
                    bool vx0 = (x0>=0)&&(x0<Wv), vx1 = (x1>=0)&&(x1<Wv);
                    int iy0 = vy0? y0:0, iy1 = vy1? y1:0;
                    int ix0 = vx0? x0:0, ix1 = vx1? x1:0;
                    const float* dwf = (const float*)dwq;
#pragma unroll
                    for (int ci = 0; ci < 8; ci++) {
                        const float* xc = xb + (size_t)ci*HWv;
                        float g00 = (vy0&&vx0)? xc[iy0*Wv+ix0] : 0.f;
                        float g01 = (vy0&&vx1)? xc[iy0*Wv+ix1] : 0.f;
                        float g10 = (vy1&&vx0)? xc[iy1*Wv+ix0] : 0.f;
                        float g11 = (vy1&&vx1)? xc[iy1*Wv+ix1] : 0.f;
                        float v = w00*g00 + w01*g01 + w10*g10 + w11*g11;
                        acc[ci] = fmaf(dwf[ci], v, acc[ci]);
                    }
                }
            }
        }
    }
    __half* outp = g_dsum + (size_t)(b*Cv + c0)*HWv + pix;
#pragma unroll
    for (int ci = 0; ci < 8; ci++) outp[(size_t)ci*HWv] = __float2half(acc[ci]);
}

// ---------------------------------------------------------------------------
// Kernel 4: out = bn5(bias(fin_w @ dsum)) * x, tiled GEMM (fp16 DS, R15 best).
// ---------------------------------------------------------------------------
__global__ __launch_bounds__(256)
void k_final(const float* __restrict__ x,
             const float* __restrict__ fw, const float* __restrict__ fb,
             const float* __restrict__ s5, const float* __restrict__ b5,
             float* __restrict__ out)
{
    __shared__ float  FWs[64*34];   // FWs[cin*34+co] = fw[(cog*32+co)*64+cin]
    __shared__ __half DS[64*64];    // DS[cin*64+p] (fp16)
    int tid = threadIdx.x;
    int b   = blockIdx.z;
    int cog = blockIdx.y;          // cout half: couts cog*32 .. cog*32+31
    int pix0 = blockIdx.x*64;

    const float* fwh = fw + (size_t)cog*32*64;
    for (int i = tid; i < 2048; i += 256) {
        int co = i >> 6, cin = i & 63;
        FWs[cin*34 + co] = fwh[i];
    }
    const __half* dp = g_dsum + (size_t)b*Cv*HWv + pix0;
    for (int i = tid; i < 512; i += 256) {
        int cin = i >> 3, p8 = i & 7;
        ((uint4*)DS)[cin*8 + p8] = *(const uint4*)(dp + (size_t)cin*HWv + p8*8);
    }
    __syncthreads();

    int tp = tid & 15;        // pixels tp*4 .. tp*4+3
    int tc = tid >> 4;        // local couts tc*2, tc*2+1
    float4 a0 = {0,0,0,0}, a1 = {0,0,0,0};

#pragma unroll 8
    for (int cin = 0; cin < 64; cin++) {
        uint2 u = *(const uint2*)&DS[cin*64 + tp*4];
        float2 dlo = __half22float2(*(const __half2*)&u.x);
        float2 dhi = __half22float2(*(const __half2*)&u.y);
        float2 w = *(const float2*)&FWs[cin*34 + tc*2];
        a0.x = fmaf(w.x, dlo.x, a0.x); a0.y = fmaf(w.x, dlo.y, a0.y);
        a0.z = fmaf(w.x, dhi.x, a0.z); a0.w = fmaf(w.x, dhi.y, a0.w);
        a1.x = fmaf(w.y, dlo.x, a1.x); a1.y = fmaf(w.y, dlo.y, a1.y);
        a1.z = fmaf(w.y, dhi.x, a1.z); a1.w = fmaf(w.y, dhi.y, a1.w);
    }

    float4 accs[2] = {a0, a1};
#pragma unroll
    for (int i = 0; i < 2; i++) {
        int j = cog*32 + tc*2 + i;
        float sc = s5[j], fbj = fb[j], bbj = b5[j];
        size_t o = (size_t)(b*Cv + j)*HWv + pix0 + tp*4;
        float4 xv = *(const float4*)(x + o);
        float4 r;
        r.x = fmaf(sc, accs[i].x + fbj, bbj) * xv.x;
        r.y = fmaf(sc, accs[i].y + fbj, bbj) * xv.y;
        r.z = fmaf(sc, accs[i].z + fbj, bbj) * xv.z;
        r.w = fmaf(sc, accs[i].w + fbj, bbj) * xv.w;
        *(float4*)(out + o) = r;
    }
}

// ---------------------------------------------------------------------------
extern "C" void kernel_launch(void* const* d_in, const int* in_sizes, int n_in,
                              void* d_out, int out_size)
{
    int ix, i_off1w, i_off1b, i_bn1s, i_bn1b, i_off2w, i_off2b, i_bn2s, i_bn2b,
        i_off3w, i_off3b, i_bn3s, i_bn3b, i_balw, i_balb, i_bn4s, i_bn4b,
        i_dw2, i_dw3, i_dw4, i_dw5, i_finw, i_finb, i_bn5s, i_bn5b;

    if (in_sizes[0] == Bv*Cv*HWv) {
        ix=0;  i_off1w=1;  i_off1b=2;  i_bn1s=3;  i_bn1b=4;
        i_off2w=5;  i_off2b=6;  i_bn2s=7;  i_bn2b=8;
        i_off3w=9;  i_off3b=10; i_bn3s=11; i_bn3b=12;
        i_balw=13; i_balb=14; i_bn4s=15; i_bn4b=16;
        i_dw2=17; i_dw3=18; i_dw4=19; i_dw5=20;
        i_finw=21; i_finb=22; i_bn5s=23; i_bn5b=24;
    } else {
        i_balb=0; i_balw=1; i_bn1b=2; i_bn1s=3; i_bn2b=4; i_bn2s=5;
        i_bn3b=6; i_bn3s=7; i_bn4b=8; i_bn4s=9; i_bn5b=10; i_bn5s=11;
        i_dw2=12; i_dw3=13; i_dw4=14; i_dw5=15;
        i_finb=16; i_finw=17; i_off1b=18; i_off1w=19;
        i_off2b=20; i_off2w=21; i_off3b=22; i_off3w=23; ix=24;
    }

    const float* x      = (const float*)d_in[ix];
    const float* off1_w = (const float*)d_in[i_off1w];
    const float* off1_b = (const float*)d_in[i_off1b];
    const float* bn1_s  = (const float*)d_in[i_bn1s];
    const float* bn1_b  = (const float*)d_in[i_bn1b];
    const float* off2_w = (const float*)d_in[i_off2w];
    const float* off2_b = (const float*)d_in[i_off2b];
    const float* bn2_s  = (const float*)d_in[i_bn2s];
    const float* bn2_b  = (const float*)d_in[i_bn2b];
    const float* off3_w = (const float*)d_in[i_off3w];
    const float* off3_b = (const float*)d_in[i_off3b];
    const float* bn3_s  = (const float*)d_in[i_bn3s];
    const float* bn3_b  = (const float*)d_in[i_bn3b];
    const float* bal_w  = (const float*)d_in[i_balw];
    const float* bal_b  = (const float*)d_in[i_balb];
    const float* bn4_s  = (const float*)d_in[i_bn4s];
    const float* bn4_b  = (const float*)d_in[i_bn4b];
    const float* dw2    = (const float*)d_in[i_dw2];
    const float* dw3    = (const float*)d_in[i_dw3];
    const float* dw4    = (const float*)d_in[i_dw4];
    const float* dw5    = (const float*)d_in[i_dw5];
    const float* fin_w  = (const float*)d_in[i_finw];
    const float* fin_b  = (const float*)d_in[i_finb];
    const float* bn5_s  = (const float*)d_in[i_bn5s];
    const float* bn5_b  = (const float*)d_in[i_bn5b];
    float* out = (float*)d_out;

    dim3 blk(32, 8);
    k_branch<<<dim3(1, 16, Bv*Cv), blk>>>(x,
        off1_w, off1_b, bn1_s, bn1_b,
        off2_w, off2_b, bn2_s, bn2_b,
        off3_w, off3_b, bn3_s, bn3_b);
    k_off<<<dim3(HWv/64, Bv), 128>>>(bal_w, bal_b, bn4_s, bn4_b);
    k_deform<<<dim3(4, 16, Bv*8), blk>>>(x, dw2, dw3, dw4, dw5);
    k_final<<<dim3(HWv/64, 2, Bv), 256>>>(x, fin_w, fin_b, bn5_s, bn5_b, out);
}